// round 2
// baseline (speedup 1.0000x reference)
#include <cuda_runtime.h>

#define BB  4
#define CC  512
#define LL  1024
#define HH  8
#define DD  64
#define FCC 2048
#define NLL 4
#define WW  4
#define EPSC 1e-6f
#define SCALEC 0.125f   // 64^-0.5

// ---------------- scratch (static device memory; no allocations) ----------------
__device__ float g_x[BB*CC*LL];
__device__ float g_q[BB*CC*LL];
__device__ float g_k[BB*CC*LL];
__device__ float g_v[BB*CC*LL];
__device__ float g_a[BB*CC*LL];
__device__ float g_t[BB*CC*LL];
__device__ float g_h[(size_t)BB*FCC*LL];

// ---------------- elementwise: y = x * mask (mask broadcast over channels) -------
__global__ void maskmul_kernel(const float* __restrict__ X, const float* __restrict__ msk,
                               float* __restrict__ Y) {
    int i = blockIdx.x * 256 + threadIdx.x;          // total = BB*CC*LL = 2^21
    int l = i & (LL - 1);
    int b = i / (CC * LL);
    Y[i] = X[i] * msk[b * LL + l];
}

// ---------------- SGEMM: Y[b] = W[M,K] @ X[b][K,N] + bias, optional relu/mask ----
// flags: 1 = multiply X columns by mask, 2 = relu, 4 = multiply output cols by mask
__global__ __launch_bounds__(256) void gemm_kernel(
    const float* __restrict__ Wm, const float* __restrict__ X,
    const float* __restrict__ bias, const float* __restrict__ msk,
    float* __restrict__ Y, int M, int N, int K, int flags)
{
    __shared__ float As[16][132];   // [k][m], padded
    __shared__ float Bs[16][128];   // [k][n]

    const int tid = threadIdx.x;
    const int tx = tid & 15, ty = tid >> 4;
    const int bm = blockIdx.y * 128, bn = blockIdx.x * 128;

    const float* Wp = Wm + (size_t)bm * K;
    const float* Xp = X + (size_t)blockIdx.z * K * N + bn;
    const float* mp = msk ? (msk + (size_t)blockIdx.z * LL) : nullptr;

    float colmask = (flags & 1) ? mp[bn + (tid & 127)] : 1.0f;

    float acc[8][8];
    #pragma unroll
    for (int i = 0; i < 8; i++)
        #pragma unroll
        for (int j = 0; j < 8; j++) acc[i][j] = 0.f;

    for (int k0 = 0; k0 < K; k0 += 16) {
        #pragma unroll
        for (int i = 0; i < 8; i++) {
            int mr = (tid >> 4) + i * 16;
            As[tid & 15][mr] = Wp[(size_t)mr * K + k0 + (tid & 15)];
        }
        #pragma unroll
        for (int i = 0; i < 8; i++) {
            int kr = (tid >> 7) + i * 2;
            Bs[kr][tid & 127] = Xp[(size_t)(k0 + kr) * N + (tid & 127)] * colmask;
        }
        __syncthreads();
        #pragma unroll
        for (int k = 0; k < 16; k++) {
            float4 a0 = *(const float4*)&As[k][ty * 8];
            float4 a1 = *(const float4*)&As[k][ty * 8 + 4];
            float4 b0 = *(const float4*)&Bs[k][tx * 8];
            float4 b1 = *(const float4*)&Bs[k][tx * 8 + 4];
            float av[8] = {a0.x,a0.y,a0.z,a0.w,a1.x,a1.y,a1.z,a1.w};
            float bv[8] = {b0.x,b0.y,b0.z,b0.w,b1.x,b1.y,b1.z,b1.w};
            #pragma unroll
            for (int i = 0; i < 8; i++)
                #pragma unroll
                for (int j = 0; j < 8; j++)
                    acc[i][j] = fmaf(av[i], bv[j], acc[i][j]);
        }
        __syncthreads();
    }

    const bool relu = flags & 2;
    float om8[8];
    #pragma unroll
    for (int j = 0; j < 8; j++)
        om8[j] = (flags & 4) ? mp[bn + tx * 8 + j] : 1.0f;

    float* Yb = Y + (size_t)blockIdx.z * M * N;
    #pragma unroll
    for (int i = 0; i < 8; i++) {
        int m = bm + ty * 8 + i;
        float bvv = bias[m];
        float o[8];
        #pragma unroll
        for (int j = 0; j < 8; j++) {
            float v = acc[i][j] + bvv;
            if (relu) v = fmaxf(v, 0.f);
            o[j] = v * om8[j];
        }
        float* yr = Yb + (size_t)m * N + bn + tx * 8;
        *(float4*)yr       = make_float4(o[0], o[1], o[2], o[3]);
        *(float4*)(yr + 4) = make_float4(o[4], o[5], o[6], o[7]);
    }
}

// ---------------- fused attention: full softmax + windowed rel-k/rel-v ----------
// grid: (L/64, H, B), 256 threads.
// Phase A: S = (q*scale)·K^T + rel_k bias (|diff|<=W) ; mask ; online softmax
// Phase B: acc += P @ (V + rel_v[diff] within window) ; final /= l_i
__global__ __launch_bounds__(256) void attn_kernel(
    const float* __restrict__ Q, const float* __restrict__ Kk,
    const float* __restrict__ V, const float* __restrict__ msk,
    const float* __restrict__ relk, const float* __restrict__ relv,
    float* __restrict__ O)
{
    extern __shared__ float smem[];
    float* qs  = smem;               // [64][65]
    float* kv  = qs  + 64 * 65;      // [64][65]
    float* ps  = kv  + 64 * 65;      // [64][64]
    float* rks = ps  + 64 * 64;      // [9][64]
    float* rvs = rks + 9 * 64;       // [9][64]

    const int tid = threadIdx.x;
    const int b = blockIdx.z, h = blockIdx.y;
    const int l0 = blockIdx.x * 64;

    const float* qp = Q  + ((size_t)b * CC + h * DD) * LL;
    const float* kp = Kk + ((size_t)b * CC + h * DD) * LL;
    const float* vp = V  + ((size_t)b * CC + h * DD) * LL;
    const float* mp = msk + (size_t)b * LL;

    // load q tile [64 l][64 d], scaled
    #pragma unroll
    for (int i = 0; i < 16; i++) {
        int l = tid & 63;
        int d = (tid >> 6) + i * 4;
        qs[l * 65 + d] = qp[(size_t)d * LL + l0 + l] * SCALEC;
    }
    for (int i = tid; i < 9 * 64; i += 256) { rks[i] = relk[i]; rvs[i] = relv[i]; }

    const int cg = tid & 15;   // phase A: m group  / phase B: d group
    const int rg = tid >> 4;   // row group (same rows in both phases)

    float acc[4][4];
    #pragma unroll
    for (int rr = 0; rr < 4; rr++)
        #pragma unroll
        for (int j = 0; j < 4; j++) acc[rr][j] = 0.f;
    float mi[4], li[4], rmask[4];
    #pragma unroll
    for (int rr = 0; rr < 4; rr++) { mi[rr] = -1e30f; li[rr] = 0.f; rmask[rr] = mp[l0 + rg*4 + rr]; }

    __syncthreads();

    for (int t = 0; t < LL / 64; t++) {
        const int m0 = t * 64;
        // K tile
        #pragma unroll
        for (int i = 0; i < 16; i++) {
            int m = tid & 63;
            int d = (tid >> 6) + i * 4;
            kv[m * 65 + d] = kp[(size_t)d * LL + m0 + m];
        }
        __syncthreads();

        // ---- Phase A: scores 4x4 microtile ----
        float s[4][4];
        #pragma unroll
        for (int rr = 0; rr < 4; rr++)
            #pragma unroll
            for (int mm = 0; mm < 4; mm++) s[rr][mm] = 0.f;

        #pragma unroll 8
        for (int d = 0; d < DD; d++) {
            float a0 = qs[(rg*4+0)*65 + d], a1 = qs[(rg*4+1)*65 + d];
            float a2 = qs[(rg*4+2)*65 + d], a3 = qs[(rg*4+3)*65 + d];
            float c0 = kv[(cg*4+0)*65 + d], c1 = kv[(cg*4+1)*65 + d];
            float c2 = kv[(cg*4+2)*65 + d], c3 = kv[(cg*4+3)*65 + d];
            s[0][0]=fmaf(a0,c0,s[0][0]); s[0][1]=fmaf(a0,c1,s[0][1]); s[0][2]=fmaf(a0,c2,s[0][2]); s[0][3]=fmaf(a0,c3,s[0][3]);
            s[1][0]=fmaf(a1,c0,s[1][0]); s[1][1]=fmaf(a1,c1,s[1][1]); s[1][2]=fmaf(a1,c2,s[1][2]); s[1][3]=fmaf(a1,c3,s[1][3]);
            s[2][0]=fmaf(a2,c0,s[2][0]); s[2][1]=fmaf(a2,c1,s[2][1]); s[2][2]=fmaf(a2,c2,s[2][2]); s[2][3]=fmaf(a2,c3,s[2][3]);
            s[3][0]=fmaf(a3,c0,s[3][0]); s[3][1]=fmaf(a3,c1,s[3][1]); s[3][2]=fmaf(a3,c2,s[3][2]); s[3][3]=fmaf(a3,c3,s[3][3]);
        }

        // windowed rel-k bias + mask
        #pragma unroll
        for (int rr = 0; rr < 4; rr++) {
            int gl = l0 + rg * 4 + rr;
            #pragma unroll
            for (int mm = 0; mm < 4; mm++) {
                int gm = m0 + cg * 4 + mm;
                int df = gm - gl;
                if (df >= -WW && df <= WW) {
                    const float* rp = &rks[(df + WW) * 64];
                    const float* qq = &qs[(rg*4+rr) * 65];
                    float add = 0.f;
                    #pragma unroll 8
                    for (int d = 0; d < DD; d++) add = fmaf(qq[d], rp[d], add);
                    s[rr][mm] += add;
                }
                float am = rmask[rr] * mp[gm];
                if (am == 0.f) s[rr][mm] = -1e4f;
            }
        }

        // ---- online softmax per row (reduce over 16 cg lanes) ----
        #pragma unroll
        for (int rr = 0; rr < 4; rr++) {
            float tm = fmaxf(fmaxf(s[rr][0], s[rr][1]), fmaxf(s[rr][2], s[rr][3]));
            #pragma unroll
            for (int o = 8; o >= 1; o >>= 1) tm = fmaxf(tm, __shfl_xor_sync(0xffffffffu, tm, o));
            float newm = fmaxf(mi[rr], tm);
            float corr = __expf(mi[rr] - newm);
            mi[rr] = newm;
            float p0 = __expf(s[rr][0]-newm), p1 = __expf(s[rr][1]-newm);
            float p2 = __expf(s[rr][2]-newm), p3 = __expf(s[rr][3]-newm);
            float psum = p0 + p1 + p2 + p3;
            #pragma unroll
            for (int o = 8; o >= 1; o >>= 1) psum += __shfl_xor_sync(0xffffffffu, psum, o);
            li[rr] = li[rr] * corr + psum;
            *(float4*)&ps[(rg*4+rr) * 64 + cg * 4] = make_float4(p0, p1, p2, p3);
            #pragma unroll
            for (int j = 0; j < 4; j++) acc[rr][j] *= corr;
        }
        __syncthreads();

        // V tile (reuse kv)
        #pragma unroll
        for (int i = 0; i < 16; i++) {
            int m = tid & 63;
            int d = (tid >> 6) + i * 4;
            kv[m * 65 + d] = vp[(size_t)d * LL + m0 + m];
        }
        __syncthreads();

        // ---- Phase B: acc += P @ (V + win*rel_v) ----
        #pragma unroll 4
        for (int m = 0; m < 64; m++) {
            float p0 = ps[(rg*4+0)*64 + m], p1 = ps[(rg*4+1)*64 + m];
            float p2 = ps[(rg*4+2)*64 + m], p3 = ps[(rg*4+3)*64 + m];
            float v0 = kv[m*65 + cg*4+0], v1 = kv[m*65 + cg*4+1];
            float v2 = kv[m*65 + cg*4+2], v3 = kv[m*65 + cg*4+3];
            acc[0][0]=fmaf(p0,v0,acc[0][0]); acc[0][1]=fmaf(p0,v1,acc[0][1]); acc[0][2]=fmaf(p0,v2,acc[0][2]); acc[0][3]=fmaf(p0,v3,acc[0][3]);
            acc[1][0]=fmaf(p1,v0,acc[1][0]); acc[1][1]=fmaf(p1,v1,acc[1][1]); acc[1][2]=fmaf(p1,v2,acc[1][2]); acc[1][3]=fmaf(p1,v3,acc[1][3]);
            acc[2][0]=fmaf(p2,v0,acc[2][0]); acc[2][1]=fmaf(p2,v1,acc[2][1]); acc[2][2]=fmaf(p2,v2,acc[2][2]); acc[2][3]=fmaf(p2,v3,acc[2][3]);
            acc[3][0]=fmaf(p3,v0,acc[3][0]); acc[3][1]=fmaf(p3,v1,acc[3][1]); acc[3][2]=fmaf(p3,v2,acc[3][2]); acc[3][3]=fmaf(p3,v3,acc[3][3]);
            // windowed rel_v contribution
            int gm = m0 + m;
            int base_df = gm - (l0 + rg * 4);
            if (base_df >= -WW && base_df <= WW + 3) {
                float pv[4] = {p0, p1, p2, p3};
                #pragma unroll
                for (int rr = 0; rr < 4; rr++) {
                    int df = base_df - rr;
                    if (df >= -WW && df <= WW) {
                        const float* rp = &rvs[(df + WW) * 64 + cg * 4];
                        #pragma unroll
                        for (int j = 0; j < 4; j++)
                            acc[rr][j] = fmaf(pv[rr], rp[j], acc[rr][j]);
                    }
                }
            }
        }
        __syncthreads();
    }

    // normalize + transpose through smem for coalesced store
    #pragma unroll
    for (int rr = 0; rr < 4; rr++) {
        float inv = 1.0f / li[rr];
        #pragma unroll
        for (int j = 0; j < 4; j++)
            kv[(rg*4+rr)*65 + cg*4+j] = acc[rr][j] * inv;
    }
    __syncthreads();
    float* op = O + ((size_t)b * CC + h * DD) * LL;
    #pragma unroll
    for (int i = 0; i < 16; i++) {
        int l = tid & 63;
        int d = (tid >> 6) + i * 4;
        op[(size_t)d * LL + l0 + l] = kv[l * 65 + d];
    }
}

// ---------------- fused residual add + LayerNorm over channels ------------------
// grid: (L/32, B), block (32, 8). In-place safe (each element has one owner).
__global__ void add_ln_kernel(const float* __restrict__ X, const float* __restrict__ Dl,
                              const float* __restrict__ gam, const float* __restrict__ bet,
                              float* __restrict__ Yo)
{
    int b = blockIdx.y;
    int l = blockIdx.x * 32 + threadIdx.x;
    int cg = threadIdx.y;
    const size_t base = (size_t)b * CC * LL + l;

    float s = 0.f, s2 = 0.f;
    for (int c = cg; c < CC; c += 8) {
        float v = X[base + (size_t)c * LL] + Dl[base + (size_t)c * LL];
        s += v; s2 += v * v;
    }
    __shared__ float sm[8][33], sq[8][33];
    sm[cg][threadIdx.x] = s; sq[cg][threadIdx.x] = s2;
    __syncthreads();
    float ts = 0.f, ts2 = 0.f;
    #pragma unroll
    for (int i = 0; i < 8; i++) { ts += sm[i][threadIdx.x]; ts2 += sq[i][threadIdx.x]; }
    float mean = ts * (1.0f / CC);
    float var  = ts2 * (1.0f / CC) - mean * mean;
    float rstd = rsqrtf(var + EPSC);
    for (int c = cg; c < CC; c += 8) {
        float v = X[base + (size_t)c * LL] + Dl[base + (size_t)c * LL];
        Yo[base + (size_t)c * LL] = (v - mean) * rstd * gam[c] + bet[c];
    }
}

// ---------------- host orchestration -------------------------------------------
extern "C" void kernel_launch(void* const* d_in, const int* in_sizes, int n_in,
                              void* d_out, int out_size)
{
    const float* x    = (const float*)d_in[0];
    const float* mask = (const float*)d_in[1];
    const float* wq = (const float*)d_in[2];  const float* bq = (const float*)d_in[3];
    const float* wk = (const float*)d_in[4];  const float* bk = (const float*)d_in[5];
    const float* wv = (const float*)d_in[6];  const float* bv = (const float*)d_in[7];
    const float* wo = (const float*)d_in[8];  const float* bo = (const float*)d_in[9];
    const float* relk = (const float*)d_in[10];
    const float* relv = (const float*)d_in[11];
    const float* ln1g = (const float*)d_in[12]; const float* ln1b = (const float*)d_in[13];
    const float* w1 = (const float*)d_in[14]; const float* b1 = (const float*)d_in[15];
    const float* w2 = (const float*)d_in[16]; const float* b2 = (const float*)d_in[17];
    const float* ln2g = (const float*)d_in[18]; const float* ln2b = (const float*)d_in[19];

    float *px, *pq, *pk, *pv, *pa, *pt, *ph;
    cudaGetSymbolAddress((void**)&px, g_x);
    cudaGetSymbolAddress((void**)&pq, g_q);
    cudaGetSymbolAddress((void**)&pk, g_k);
    cudaGetSymbolAddress((void**)&pv, g_v);
    cudaGetSymbolAddress((void**)&pa, g_a);
    cudaGetSymbolAddress((void**)&pt, g_t);
    cudaGetSymbolAddress((void**)&ph, g_h);

    const size_t attn_smem = (size_t)(64*65*2 + 64*64 + 9*64*2) * sizeof(float);
    cudaFuncSetAttribute(attn_kernel, cudaFuncAttributeMaxDynamicSharedMemorySize, (int)attn_smem);

    const int nElem = BB * CC * LL;
    maskmul_kernel<<<nElem / 256, 256>>>(x, mask, px);

    dim3 gP(LL / 128, CC / 128, BB);       // (8, 4, 4)
    dim3 gF1(LL / 128, FCC / 128, BB);     // (8, 16, 4)
    dim3 gAttn(LL / 64, HH, BB);           // (16, 8, 4)
    dim3 gLN(LL / 32, BB);
    dim3 bLN(32, 8);

    for (int i = 0; i < NLL; i++) {
        const float* Wq = wq + (size_t)i * CC * CC;
        const float* Wk = wk + (size_t)i * CC * CC;
        const float* Wv = wv + (size_t)i * CC * CC;
        const float* Wo = wo + (size_t)i * CC * CC;
        const float* W1 = w1 + (size_t)i * FCC * CC;
        const float* W2 = w2 + (size_t)i * CC * FCC;

        gemm_kernel<<<gP, 256>>>(Wq, px, bq + i*CC, nullptr, pq, CC, LL, CC, 0);
        gemm_kernel<<<gP, 256>>>(Wk, px, bk + i*CC, nullptr, pk, CC, LL, CC, 0);
        gemm_kernel<<<gP, 256>>>(Wv, px, bv + i*CC, nullptr, pv, CC, LL, CC, 0);

        attn_kernel<<<gAttn, 256, attn_smem>>>(pq, pk, pv, mask,
                                               relk + (size_t)i * 9 * DD,
                                               relv + (size_t)i * 9 * DD, pa);

        gemm_kernel<<<gP, 256>>>(Wo, pa, bo + i*CC, nullptr, pt, CC, LL, CC, 0);
        add_ln_kernel<<<gLN, bLN>>>(px, pt, ln1g + i*CC, ln1b + i*CC, px);

        gemm_kernel<<<gF1, 256>>>(W1, px, b1 + i*FCC, mask, ph, FCC, LL, CC, 1 | 2 | 4);
        gemm_kernel<<<gP, 256>>>(W2, ph, b2 + i*CC, mask, pt, CC, LL, FCC, 4);
        add_ln_kernel<<<gLN, bLN>>>(px, pt, ln2g + i*CC, ln2b + i*CC, px);
    }

    maskmul_kernel<<<nElem / 256, 256>>>(px, mask, (float*)d_out);
}

// round 3
// speedup vs baseline: 2.0071x; 2.0071x over previous
#include <cuda_runtime.h>
#include <stdint.h>

#define BB  4
#define CC  512
#define LL  1024
#define HH  8
#define DD  64
#define FCC 2048
#define NLL 4
#define WW  4
#define EPSC 1e-6f
#define SCALEC 0.125f   // 64^-0.5

// ---------------- scratch (static device memory; no allocations) ----------------
__device__ float g_x[BB*CC*LL];
__device__ float g_q[BB*CC*LL];
__device__ float g_k[BB*CC*LL];
__device__ float g_v[BB*CC*LL];
__device__ float g_a[BB*CC*LL];
__device__ float g_t[BB*CC*LL];
__device__ float g_h[(size_t)BB*FCC*LL];

// ---------------- elementwise: y = x * mask (mask broadcast over channels) -------
__global__ void maskmul_kernel(const float* __restrict__ X, const float* __restrict__ msk,
                               float* __restrict__ Y) {
    int i = blockIdx.x * 256 + threadIdx.x;          // total = BB*CC*LL = 2^21
    int l = i & (LL - 1);
    int b = i / (CC * LL);
    Y[i] = X[i] * msk[b * LL + l];
}

// ---------------- tf32 helpers ---------------------------------------------------
__device__ __forceinline__ uint32_t f2tf(float x) {
    uint32_t t;
    asm volatile("cvt.rna.tf32.f32 %0, %1;" : "=r"(t) : "f"(x));
    return t;
}

__device__ __forceinline__ void mma_tf32(float* c, const uint32_t* a, const uint32_t* b) {
    asm volatile(
        "mma.sync.aligned.m16n8k8.row.col.f32.tf32.tf32.f32 "
        "{%0,%1,%2,%3}, {%4,%5,%6,%7}, {%8,%9}, {%0,%1,%2,%3};\n"
        : "+f"(c[0]), "+f"(c[1]), "+f"(c[2]), "+f"(c[3])
        : "r"(a[0]), "r"(a[1]), "r"(a[2]), "r"(a[3]), "r"(b[0]), "r"(b[1]));
}

// ---------------- tf32 tensor-core GEMM -----------------------------------------
// Y[b] = W[M,K] @ X[b][K,N] + bias ; flags: 1=mask X cols, 2=relu, 4=mask out cols
// Supports up to 3 weight/bias/output sets selected by blockIdx.z / BB (QKV fusion).
// Block: 128 threads (4 warps, 2x2), block tile 128x128, warp tile 64x64, k-step 16.
__global__ __launch_bounds__(128, 2) void gemm_tc_kernel(
    const float* __restrict__ W0, const float* __restrict__ W1p, const float* __restrict__ W2p,
    const float* __restrict__ c0, const float* __restrict__ c1, const float* __restrict__ c2,
    const float* __restrict__ X, const float* __restrict__ msk,
    float* __restrict__ Y0, float* __restrict__ Y1p, float* __restrict__ Y2p,
    int M, int N, int K, int flags)
{
    __shared__ float As[2][16][136];   // [buf][k][m]
    __shared__ float Bs[2][16][136];   // [buf][k][n]

    const int tid  = threadIdx.x;
    const int mat  = blockIdx.z / BB;
    const int b    = blockIdx.z % BB;
    const float* Wm   = (mat == 0) ? W0 : (mat == 1 ? W1p : W2p);
    const float* bias = (mat == 0) ? c0 : (mat == 1 ? c1 : c2);
    float*       Y    = (mat == 0) ? Y0 : (mat == 1 ? Y1p : Y2p);

    const int bm = blockIdx.y * 128, bn = blockIdx.x * 128;
    const float* mp = msk + (size_t)b * LL;

    const float* Ap = Wm + (size_t)(bm + tid) * K;
    const int bk = tid >> 5;          // 0..3 : base k row for B staging
    const int bn4 = (tid & 31) * 4;   // n offset for B staging
    const float* Bp = X + (size_t)b * K * N + bn + bn4;

    float4 cm4 = make_float4(1.f, 1.f, 1.f, 1.f);
    if (flags & 1) cm4 = *(const float4*)&mp[bn + bn4];

    const int lane = tid & 31, warp = tid >> 5;
    const int wm = (warp >> 1) * 64, wn = (warp & 1) * 64;
    const int lm = lane >> 2, lk = lane & 3;

    float acc[4][8][4];
    #pragma unroll
    for (int i = 0; i < 4; i++)
        #pragma unroll
        for (int j = 0; j < 8; j++)
            #pragma unroll
            for (int r = 0; r < 4; r++) acc[i][j][r] = 0.f;

    float4 ra[4], rb[4];

    #define LOADG(K0) do { \
        _Pragma("unroll") \
        for (int i = 0; i < 4; i++) ra[i] = *(const float4*)(Ap + (K0) + i * 4); \
        _Pragma("unroll") \
        for (int i = 0; i < 4; i++) rb[i] = *(const float4*)(Bp + (size_t)((K0) + bk + 4 * i) * N); \
    } while (0)

    #define STORES(BUF) do { \
        _Pragma("unroll") \
        for (int i = 0; i < 4; i++) { \
            As[BUF][i*4+0][tid] = __uint_as_float(f2tf(ra[i].x)); \
            As[BUF][i*4+1][tid] = __uint_as_float(f2tf(ra[i].y)); \
            As[BUF][i*4+2][tid] = __uint_as_float(f2tf(ra[i].z)); \
            As[BUF][i*4+3][tid] = __uint_as_float(f2tf(ra[i].w)); \
        } \
        _Pragma("unroll") \
        for (int i = 0; i < 4; i++) { \
            float4 t; \
            t.x = __uint_as_float(f2tf(rb[i].x * cm4.x)); \
            t.y = __uint_as_float(f2tf(rb[i].y * cm4.y)); \
            t.z = __uint_as_float(f2tf(rb[i].z * cm4.z)); \
            t.w = __uint_as_float(f2tf(rb[i].w * cm4.w)); \
            *(float4*)&Bs[BUF][bk + 4 * i][bn4] = t; \
        } \
    } while (0)

    #define COMPUTE(BUF) do { \
        _Pragma("unroll") \
        for (int ks = 0; ks < 16; ks += 8) { \
            uint32_t af[4][4], bf[8][2]; \
            _Pragma("unroll") \
            for (int mt = 0; mt < 4; mt++) { \
                af[mt][0] = __float_as_uint(As[BUF][ks + lk    ][wm + mt*16 + lm    ]); \
                af[mt][1] = __float_as_uint(As[BUF][ks + lk    ][wm + mt*16 + lm + 8]); \
                af[mt][2] = __float_as_uint(As[BUF][ks + lk + 4][wm + mt*16 + lm    ]); \
                af[mt][3] = __float_as_uint(As[BUF][ks + lk + 4][wm + mt*16 + lm + 8]); \
            } \
            _Pragma("unroll") \
            for (int nt = 0; nt < 8; nt++) { \
                bf[nt][0] = __float_as_uint(Bs[BUF][ks + lk    ][wn + nt*8 + lm]); \
                bf[nt][1] = __float_as_uint(Bs[BUF][ks + lk + 4][wn + nt*8 + lm]); \
            } \
            _Pragma("unroll") \
            for (int mt = 0; mt < 4; mt++) \
                _Pragma("unroll") \
                for (int nt = 0; nt < 8; nt++) \
                    mma_tf32(acc[mt][nt], af[mt], bf[nt]); \
        } \
    } while (0)

    LOADG(0);
    STORES(0);
    __syncthreads();

    const int nIter = K / 16;
    for (int it = 0; it < nIter; it++) {
        const int cur = it & 1;
        if (it + 1 < nIter) {
            LOADG((it + 1) * 16);
        }
        COMPUTE(cur);
        if (it + 1 < nIter) {
            STORES(cur ^ 1);
        }
        __syncthreads();
    }

    // ---------------- epilogue ----------------
    const bool relu = flags & 2;
    const bool omask = flags & 4;
    float* Yb = Y + (size_t)b * M * N;
    #pragma unroll
    for (int mt = 0; mt < 4; mt++) {
        #pragma unroll
        for (int half = 0; half < 2; half++) {
            int m = bm + wm + mt * 16 + lm + half * 8;
            float bv = bias[m];
            #pragma unroll
            for (int nt = 0; nt < 8; nt++) {
                int n = bn + wn + nt * 8 + lk * 2;
                float v0 = acc[mt][nt][half * 2 + 0] + bv;
                float v1 = acc[mt][nt][half * 2 + 1] + bv;
                if (relu) { v0 = fmaxf(v0, 0.f); v1 = fmaxf(v1, 0.f); }
                if (omask) { v0 *= mp[n]; v1 *= mp[n + 1]; }
                float2 o = make_float2(v0, v1);
                *(float2*)&Yb[(size_t)m * N + n] = o;
            }
        }
    }
    #undef LOADG
    #undef STORES
    #undef COMPUTE
}

// ---------------- fused attention: full softmax + windowed rel-k/rel-v ----------
__global__ __launch_bounds__(256) void attn_kernel(
    const float* __restrict__ Q, const float* __restrict__ Kk,
    const float* __restrict__ V, const float* __restrict__ msk,
    const float* __restrict__ relk, const float* __restrict__ relv,
    float* __restrict__ O)
{
    extern __shared__ float smem[];
    float* qs  = smem;               // [64][65]
    float* kv  = qs  + 64 * 65;      // [64][65]
    float* ps  = kv  + 64 * 65;      // [64][64]
    float* rks = ps  + 64 * 64;      // [9][64]
    float* rvs = rks + 9 * 64;       // [9][64]

    const int tid = threadIdx.x;
    const int b = blockIdx.z, h = blockIdx.y;
    const int l0 = blockIdx.x * 64;

    const float* qp = Q  + ((size_t)b * CC + h * DD) * LL;
    const float* kp = Kk + ((size_t)b * CC + h * DD) * LL;
    const float* vp = V  + ((size_t)b * CC + h * DD) * LL;
    const float* mp = msk + (size_t)b * LL;

    #pragma unroll
    for (int i = 0; i < 16; i++) {
        int l = tid & 63;
        int d = (tid >> 6) + i * 4;
        qs[l * 65 + d] = qp[(size_t)d * LL + l0 + l] * SCALEC;
    }
    for (int i = tid; i < 9 * 64; i += 256) { rks[i] = relk[i]; rvs[i] = relv[i]; }

    const int cg = tid & 15;
    const int rg = tid >> 4;

    float acc[4][4];
    #pragma unroll
    for (int rr = 0; rr < 4; rr++)
        #pragma unroll
        for (int j = 0; j < 4; j++) acc[rr][j] = 0.f;
    float mi[4], li[4], rmask[4];
    #pragma unroll
    for (int rr = 0; rr < 4; rr++) { mi[rr] = -1e30f; li[rr] = 0.f; rmask[rr] = mp[l0 + rg*4 + rr]; }

    __syncthreads();

    for (int t = 0; t < LL / 64; t++) {
        const int m0 = t * 64;
        #pragma unroll
        for (int i = 0; i < 16; i++) {
            int m = tid & 63;
            int d = (tid >> 6) + i * 4;
            kv[m * 65 + d] = kp[(size_t)d * LL + m0 + m];
        }
        __syncthreads();

        float s[4][4];
        #pragma unroll
        for (int rr = 0; rr < 4; rr++)
            #pragma unroll
            for (int mm = 0; mm < 4; mm++) s[rr][mm] = 0.f;

        #pragma unroll 8
        for (int d = 0; d < DD; d++) {
            float a0 = qs[(rg*4+0)*65 + d], a1 = qs[(rg*4+1)*65 + d];
            float a2 = qs[(rg*4+2)*65 + d], a3 = qs[(rg*4+3)*65 + d];
            float c0 = kv[(cg*4+0)*65 + d], c1 = kv[(cg*4+1)*65 + d];
            float c2 = kv[(cg*4+2)*65 + d], c3 = kv[(cg*4+3)*65 + d];
            s[0][0]=fmaf(a0,c0,s[0][0]); s[0][1]=fmaf(a0,c1,s[0][1]); s[0][2]=fmaf(a0,c2,s[0][2]); s[0][3]=fmaf(a0,c3,s[0][3]);
            s[1][0]=fmaf(a1,c0,s[1][0]); s[1][1]=fmaf(a1,c1,s[1][1]); s[1][2]=fmaf(a1,c2,s[1][2]); s[1][3]=fmaf(a1,c3,s[1][3]);
            s[2][0]=fmaf(a2,c0,s[2][0]); s[2][1]=fmaf(a2,c1,s[2][1]); s[2][2]=fmaf(a2,c2,s[2][2]); s[2][3]=fmaf(a2,c3,s[2][3]);
            s[3][0]=fmaf(a3,c0,s[3][0]); s[3][1]=fmaf(a3,c1,s[3][1]); s[3][2]=fmaf(a3,c2,s[3][2]); s[3][3]=fmaf(a3,c3,s[3][3]);
        }

        #pragma unroll
        for (int rr = 0; rr < 4; rr++) {
            int gl = l0 + rg * 4 + rr;
            #pragma unroll
            for (int mm = 0; mm < 4; mm++) {
                int gm = m0 + cg * 4 + mm;
                int df = gm - gl;
                if (df >= -WW && df <= WW) {
                    const float* rp = &rks[(df + WW) * 64];
                    const float* qq = &qs[(rg*4+rr) * 65];
                    float add = 0.f;
                    #pragma unroll 8
                    for (int d = 0; d < DD; d++) add = fmaf(qq[d], rp[d], add);
                    s[rr][mm] += add;
                }
                float am = rmask[rr] * mp[gm];
                if (am == 0.f) s[rr][mm] = -1e4f;
            }
        }

        #pragma unroll
        for (int rr = 0; rr < 4; rr++) {
            float tm = fmaxf(fmaxf(s[rr][0], s[rr][1]), fmaxf(s[rr][2], s[rr][3]));
            #pragma unroll
            for (int o = 8; o >= 1; o >>= 1) tm = fmaxf(tm, __shfl_xor_sync(0xffffffffu, tm, o));
            float newm = fmaxf(mi[rr], tm);
            float corr = __expf(mi[rr] - newm);
            mi[rr] = newm;
            float p0 = __expf(s[rr][0]-newm), p1 = __expf(s[rr][1]-newm);
            float p2 = __expf(s[rr][2]-newm), p3 = __expf(s[rr][3]-newm);
            float psum = p0 + p1 + p2 + p3;
            #pragma unroll
            for (int o = 8; o >= 1; o >>= 1) psum += __shfl_xor_sync(0xffffffffu, psum, o);
            li[rr] = li[rr] * corr + psum;
            *(float4*)&ps[(rg*4+rr) * 64 + cg * 4] = make_float4(p0, p1, p2, p3);
            #pragma unroll
            for (int j = 0; j < 4; j++) acc[rr][j] *= corr;
        }
        __syncthreads();

        #pragma unroll
        for (int i = 0; i < 16; i++) {
            int m = tid & 63;
            int d = (tid >> 6) + i * 4;
            kv[m * 65 + d] = vp[(size_t)d * LL + m0 + m];
        }
        __syncthreads();

        #pragma unroll 4
        for (int m = 0; m < 64; m++) {
            float p0 = ps[(rg*4+0)*64 + m], p1 = ps[(rg*4+1)*64 + m];
            float p2 = ps[(rg*4+2)*64 + m], p3 = ps[(rg*4+3)*64 + m];
            float v0 = kv[m*65 + cg*4+0], v1 = kv[m*65 + cg*4+1];
            float v2 = kv[m*65 + cg*4+2], v3 = kv[m*65 + cg*4+3];
            acc[0][0]=fmaf(p0,v0,acc[0][0]); acc[0][1]=fmaf(p0,v1,acc[0][1]); acc[0][2]=fmaf(p0,v2,acc[0][2]); acc[0][3]=fmaf(p0,v3,acc[0][3]);
            acc[1][0]=fmaf(p1,v0,acc[1][0]); acc[1][1]=fmaf(p1,v1,acc[1][1]); acc[1][2]=fmaf(p1,v2,acc[1][2]); acc[1][3]=fmaf(p1,v3,acc[1][3]);
            acc[2][0]=fmaf(p2,v0,acc[2][0]); acc[2][1]=fmaf(p2,v1,acc[2][1]); acc[2][2]=fmaf(p2,v2,acc[2][2]); acc[2][3]=fmaf(p2,v3,acc[2][3]);
            acc[3][0]=fmaf(p3,v0,acc[3][0]); acc[3][1]=fmaf(p3,v1,acc[3][1]); acc[3][2]=fmaf(p3,v2,acc[3][2]); acc[3][3]=fmaf(p3,v3,acc[3][3]);
            int gm = m0 + m;
            int base_df = gm - (l0 + rg * 4);
            if (base_df >= -WW && base_df <= WW + 3) {
                float pv[4] = {p0, p1, p2, p3};
                #pragma unroll
                for (int rr = 0; rr < 4; rr++) {
                    int df = base_df - rr;
                    if (df >= -WW && df <= WW) {
                        const float* rp = &rvs[(df + WW) * 64 + cg * 4];
                        #pragma unroll
                        for (int j = 0; j < 4; j++)
                            acc[rr][j] = fmaf(pv[rr], rp[j], acc[rr][j]);
                    }
                }
            }
        }
        __syncthreads();
    }

    #pragma unroll
    for (int rr = 0; rr < 4; rr++) {
        float inv = 1.0f / li[rr];
        #pragma unroll
        for (int j = 0; j < 4; j++)
            kv[(rg*4+rr)*65 + cg*4+j] = acc[rr][j] * inv;
    }
    __syncthreads();
    float* op = O + ((size_t)b * CC + h * DD) * LL;
    #pragma unroll
    for (int i = 0; i < 16; i++) {
        int l = tid & 63;
        int d = (tid >> 6) + i * 4;
        op[(size_t)d * LL + l0 + l] = kv[l * 65 + d];
    }
}

// ---------------- fused residual add + LayerNorm over channels ------------------
__global__ void add_ln_kernel(const float* __restrict__ X, const float* __restrict__ Dl,
                              const float* __restrict__ gam, const float* __restrict__ bet,
                              float* __restrict__ Yo)
{
    int b = blockIdx.y;
    int l = blockIdx.x * 32 + threadIdx.x;
    int cg = threadIdx.y;
    const size_t base = (size_t)b * CC * LL + l;

    float s = 0.f, s2 = 0.f;
    for (int c = cg; c < CC; c += 8) {
        float v = X[base + (size_t)c * LL] + Dl[base + (size_t)c * LL];
        s += v; s2 += v * v;
    }
    __shared__ float sm[8][33], sq[8][33];
    sm[cg][threadIdx.x] = s; sq[cg][threadIdx.x] = s2;
    __syncthreads();
    float ts = 0.f, ts2 = 0.f;
    #pragma unroll
    for (int i = 0; i < 8; i++) { ts += sm[i][threadIdx.x]; ts2 += sq[i][threadIdx.x]; }
    float mean = ts * (1.0f / CC);
    float var  = ts2 * (1.0f / CC) - mean * mean;
    float rstd = rsqrtf(var + EPSC);
    for (int c = cg; c < CC; c += 8) {
        float v = X[base + (size_t)c * LL] + Dl[base + (size_t)c * LL];
        Yo[base + (size_t)c * LL] = (v - mean) * rstd * gam[c] + bet[c];
    }
}

// ---------------- host orchestration -------------------------------------------
extern "C" void kernel_launch(void* const* d_in, const int* in_sizes, int n_in,
                              void* d_out, int out_size)
{
    const float* x    = (const float*)d_in[0];
    const float* mask = (const float*)d_in[1];
    const float* wq = (const float*)d_in[2];  const float* bq = (const float*)d_in[3];
    const float* wk = (const float*)d_in[4];  const float* bk = (const float*)d_in[5];
    const float* wv = (const float*)d_in[6];  const float* bv = (const float*)d_in[7];
    const float* wo = (const float*)d_in[8];  const float* bo = (const float*)d_in[9];
    const float* relk = (const float*)d_in[10];
    const float* relv = (const float*)d_in[11];
    const float* ln1g = (const float*)d_in[12]; const float* ln1b = (const float*)d_in[13];
    const float* w1 = (const float*)d_in[14]; const float* b1 = (const float*)d_in[15];
    const float* w2 = (const float*)d_in[16]; const float* b2 = (const float*)d_in[17];
    const float* ln2g = (const float*)d_in[18]; const float* ln2b = (const float*)d_in[19];

    float *px, *pq, *pk, *pv, *pa, *pt, *ph;
    cudaGetSymbolAddress((void**)&px, g_x);
    cudaGetSymbolAddress((void**)&pq, g_q);
    cudaGetSymbolAddress((void**)&pk, g_k);
    cudaGetSymbolAddress((void**)&pv, g_v);
    cudaGetSymbolAddress((void**)&pa, g_a);
    cudaGetSymbolAddress((void**)&pt, g_t);
    cudaGetSymbolAddress((void**)&ph, g_h);

    const size_t attn_smem = (size_t)(64*65*2 + 64*64 + 9*64*2) * sizeof(float);
    cudaFuncSetAttribute(attn_kernel, cudaFuncAttributeMaxDynamicSharedMemorySize, (int)attn_smem);

    const int nElem = BB * CC * LL;
    maskmul_kernel<<<nElem / 256, 256>>>(x, mask, px);

    dim3 gQKV(LL / 128, CC / 128, 3 * BB);   // (8, 4, 12) — fused QKV
    dim3 gP(LL / 128, CC / 128, BB);         // (8, 4, 4)
    dim3 gF1(LL / 128, FCC / 128, BB);       // (8, 16, 4)
    dim3 gAttn(LL / 64, HH, BB);             // (16, 8, 4)
    dim3 gLN(LL / 32, BB);
    dim3 bLN(32, 8);

    for (int i = 0; i < NLL; i++) {
        const float* Wq = wq + (size_t)i * CC * CC;
        const float* Wk = wk + (size_t)i * CC * CC;
        const float* Wv = wv + (size_t)i * CC * CC;
        const float* Wo = wo + (size_t)i * CC * CC;
        const float* W1 = w1 + (size_t)i * FCC * CC;
        const float* W2 = w2 + (size_t)i * CC * FCC;

        gemm_tc_kernel<<<gQKV, 128>>>(Wq, Wk, Wv, bq + i*CC, bk + i*CC, bv + i*CC,
                                      px, mask, pq, pk, pv, CC, LL, CC, 0);

        attn_kernel<<<gAttn, 256, attn_smem>>>(pq, pk, pv, mask,
                                               relk + (size_t)i * 9 * DD,
                                               relv + (size_t)i * 9 * DD, pa);

        gemm_tc_kernel<<<gP, 128>>>(Wo, Wo, Wo, bo + i*CC, bo + i*CC, bo + i*CC,
                                    pa, mask, pt, pt, pt, CC, LL, CC, 0);
        add_ln_kernel<<<gLN, bLN>>>(px, pt, ln1g + i*CC, ln1b + i*CC, px);

        gemm_tc_kernel<<<gF1, 128>>>(W1, W1, W1, b1 + i*FCC, b1 + i*FCC, b1 + i*FCC,
                                     px, mask, ph, ph, ph, FCC, LL, CC, 1 | 2 | 4);
        gemm_tc_kernel<<<gP, 128>>>(W2, W2, W2, b2 + i*CC, b2 + i*CC, b2 + i*CC,
                                    ph, mask, pt, pt, pt, CC, LL, FCC, 4);
        add_ln_kernel<<<gLN, bLN>>>(px, pt, ln2g + i*CC, ln2b + i*CC, px);
    }

    maskmul_kernel<<<nElem / 256, 256>>>(px, mask, (float*)d_out);
}

// round 4
// speedup vs baseline: 2.7635x; 1.3768x over previous
#include <cuda_runtime.h>
#include <stdint.h>

#define BB  4
#define CC  512
#define LL  1024
#define HH  8
#define DD  64
#define FCC 2048
#define NLL 4
#define WW  4
#define EPSC 1e-6f
#define SCALEC 0.125f   // 64^-0.5

// ---------------- scratch (static device memory; no allocations) ----------------
__device__ float g_x[BB*CC*LL];
__device__ float g_q[BB*CC*LL];
__device__ float g_k[BB*CC*LL];
__device__ float g_v[BB*CC*LL];
__device__ float g_a[BB*CC*LL];
__device__ float g_t[BB*CC*LL];
__device__ float g_h[(size_t)BB*FCC*LL];

// ---------------- elementwise ----------------------------------------------------
__global__ void maskmul_kernel(const float* __restrict__ X, const float* __restrict__ msk,
                               float* __restrict__ Y) {
    int i = blockIdx.x * 256 + threadIdx.x;
    int l = i & (LL - 1);
    int b = i / (CC * LL);
    Y[i] = X[i] * msk[b * LL + l];
}

// ---------------- tf32 helpers ---------------------------------------------------
__device__ __forceinline__ uint32_t f2tf(float x) {
    uint32_t t;
    asm volatile("cvt.rna.tf32.f32 %0, %1;" : "=r"(t) : "f"(x));
    return t;
}

__device__ __forceinline__ void mma_tf32(float* c, const uint32_t* a, const uint32_t* b) {
    asm volatile(
        "mma.sync.aligned.m16n8k8.row.col.f32.tf32.tf32.f32 "
        "{%0,%1,%2,%3}, {%4,%5,%6,%7}, {%8,%9}, {%0,%1,%2,%3};\n"
        : "+f"(c[0]), "+f"(c[1]), "+f"(c[2]), "+f"(c[3])
        : "r"(a[0]), "r"(a[1]), "r"(a[2]), "r"(a[3]), "r"(b[0]), "r"(b[1]));
}

// ---------------- tf32 tensor-core GEMM (unchanged from R3) ----------------------
__global__ __launch_bounds__(128, 2) void gemm_tc_kernel(
    const float* __restrict__ W0, const float* __restrict__ W1p, const float* __restrict__ W2p,
    const float* __restrict__ c0, const float* __restrict__ c1, const float* __restrict__ c2,
    const float* __restrict__ X, const float* __restrict__ msk,
    float* __restrict__ Y0, float* __restrict__ Y1p, float* __restrict__ Y2p,
    int M, int N, int K, int flags)
{
    __shared__ float As[2][16][136];
    __shared__ float Bs[2][16][136];

    const int tid  = threadIdx.x;
    const int mat  = blockIdx.z / BB;
    const int b    = blockIdx.z % BB;
    const float* Wm   = (mat == 0) ? W0 : (mat == 1 ? W1p : W2p);
    const float* bias = (mat == 0) ? c0 : (mat == 1 ? c1 : c2);
    float*       Y    = (mat == 0) ? Y0 : (mat == 1 ? Y1p : Y2p);

    const int bm = blockIdx.y * 128, bn = blockIdx.x * 128;
    const float* mp = msk + (size_t)b * LL;

    const float* Ap = Wm + (size_t)(bm + tid) * K;
    const int bk = tid >> 5;
    const int bn4 = (tid & 31) * 4;
    const float* Bp = X + (size_t)b * K * N + bn + bn4;

    float4 cm4 = make_float4(1.f, 1.f, 1.f, 1.f);
    if (flags & 1) cm4 = *(const float4*)&mp[bn + bn4];

    const int lane = tid & 31, warp = tid >> 5;
    const int wm = (warp >> 1) * 64, wn = (warp & 1) * 64;
    const int lm = lane >> 2, lk = lane & 3;

    float acc[4][8][4];
    #pragma unroll
    for (int i = 0; i < 4; i++)
        #pragma unroll
        for (int j = 0; j < 8; j++)
            #pragma unroll
            for (int r = 0; r < 4; r++) acc[i][j][r] = 0.f;

    float4 ra[4], rb[4];

    #define LOADG(K0) do { \
        _Pragma("unroll") \
        for (int i = 0; i < 4; i++) ra[i] = *(const float4*)(Ap + (K0) + i * 4); \
        _Pragma("unroll") \
        for (int i = 0; i < 4; i++) rb[i] = *(const float4*)(Bp + (size_t)((K0) + bk + 4 * i) * N); \
    } while (0)

    #define STORES(BUF) do { \
        _Pragma("unroll") \
        for (int i = 0; i < 4; i++) { \
            As[BUF][i*4+0][tid] = __uint_as_float(f2tf(ra[i].x)); \
            As[BUF][i*4+1][tid] = __uint_as_float(f2tf(ra[i].y)); \
            As[BUF][i*4+2][tid] = __uint_as_float(f2tf(ra[i].z)); \
            As[BUF][i*4+3][tid] = __uint_as_float(f2tf(ra[i].w)); \
        } \
        _Pragma("unroll") \
        for (int i = 0; i < 4; i++) { \
            float4 t; \
            t.x = __uint_as_float(f2tf(rb[i].x * cm4.x)); \
            t.y = __uint_as_float(f2tf(rb[i].y * cm4.y)); \
            t.z = __uint_as_float(f2tf(rb[i].z * cm4.z)); \
            t.w = __uint_as_float(f2tf(rb[i].w * cm4.w)); \
            *(float4*)&Bs[BUF][bk + 4 * i][bn4] = t; \
        } \
    } while (0)

    #define COMPUTE(BUF) do { \
        _Pragma("unroll") \
        for (int ks = 0; ks < 16; ks += 8) { \
            uint32_t af[4][4], bf[8][2]; \
            _Pragma("unroll") \
            for (int mt = 0; mt < 4; mt++) { \
                af[mt][0] = __float_as_uint(As[BUF][ks + lk    ][wm + mt*16 + lm    ]); \
                af[mt][1] = __float_as_uint(As[BUF][ks + lk    ][wm + mt*16 + lm + 8]); \
                af[mt][2] = __float_as_uint(As[BUF][ks + lk + 4][wm + mt*16 + lm    ]); \
                af[mt][3] = __float_as_uint(As[BUF][ks + lk + 4][wm + mt*16 + lm + 8]); \
            } \
            _Pragma("unroll") \
            for (int nt = 0; nt < 8; nt++) { \
                bf[nt][0] = __float_as_uint(Bs[BUF][ks + lk    ][wn + nt*8 + lm]); \
                bf[nt][1] = __float_as_uint(Bs[BUF][ks + lk + 4][wn + nt*8 + lm]); \
            } \
            _Pragma("unroll") \
            for (int mt = 0; mt < 4; mt++) \
                _Pragma("unroll") \
                for (int nt = 0; nt < 8; nt++) \
                    mma_tf32(acc[mt][nt], af[mt], bf[nt]); \
        } \
    } while (0)

    LOADG(0);
    STORES(0);
    __syncthreads();

    const int nIter = K / 16;
    for (int it = 0; it < nIter; it++) {
        const int cur = it & 1;
        if (it + 1 < nIter) LOADG((it + 1) * 16);
        COMPUTE(cur);
        if (it + 1 < nIter) STORES(cur ^ 1);
        __syncthreads();
    }

    const bool relu = flags & 2;
    const bool omask = flags & 4;
    float* Yb = Y + (size_t)b * M * N;
    #pragma unroll
    for (int mt = 0; mt < 4; mt++) {
        #pragma unroll
        for (int half = 0; half < 2; half++) {
            int m = bm + wm + mt * 16 + lm + half * 8;
            float bv = bias[m];
            #pragma unroll
            for (int nt = 0; nt < 8; nt++) {
                int n = bn + wn + nt * 8 + lk * 2;
                float v0 = acc[mt][nt][half * 2 + 0] + bv;
                float v1 = acc[mt][nt][half * 2 + 1] + bv;
                if (relu) { v0 = fmaxf(v0, 0.f); v1 = fmaxf(v1, 0.f); }
                if (omask) { v0 *= mp[n]; v1 *= mp[n + 1]; }
                *(float2*)&Yb[(size_t)m * N + n] = make_float2(v0, v1);
            }
        }
    }
    #undef LOADG
    #undef STORES
    #undef COMPUTE
}

// ---------------- tensor-core flash attention ------------------------------------
// grid (L/64, H, B), 128 threads (4 warps x 16 rows). tf32 mma for QK^T and PV.
// rel_k folded as precomputed per-row bias; rel_v via tracked window probs.
__global__ __launch_bounds__(128) void attn_tc_kernel(
    const float* __restrict__ Q, const float* __restrict__ Kk,
    const float* __restrict__ V, const float* __restrict__ msk,
    const float* __restrict__ relk, const float* __restrict__ relv,
    float* __restrict__ O)
{
    extern __shared__ float smem[];
    float* qs    = smem;                 // [64][73]  Q tile [l][d] tf32 (scaled)
    float* ks_   = qs    + 64 * 73;      // [64][73]  K tile [m][d] tf32
    float* ps    = ks_   + 64 * 73;      // [64][73]  P tile [l][m] tf32 / out [l][d]
    float* vs    = ps    + 64 * 73;      // [64][76]  V tile [d][m] tf32
    float* rks   = vs    + 64 * 76;      // [9][64]
    float* rvs   = rks   + 9 * 64;       // [9][64]
    float* relb  = rvs   + 9 * 64;       // [64][12]  q.rel_k bias per (l, df)
    float* pwin  = relb  + 64 * 12;      // [64][12]  window probs (running scale)
    float* invli = pwin  + 64 * 12;      // [64]
    float* msks  = invli + 64;           // [64] column mask tile

    const int tid = threadIdx.x;
    const int lane = tid & 31, warp = tid >> 5;
    const int b = blockIdx.z, h = blockIdx.y;
    const int l0 = blockIdx.x * 64;

    const float* qp = Q  + ((size_t)b * CC + h * DD) * LL;
    const float* kp = Kk + ((size_t)b * CC + h * DD) * LL;
    const float* vp = V  + ((size_t)b * CC + h * DD) * LL;
    const float* mp = msk + (size_t)b * LL;

    // ---- one-time loads: Q (transposed, tf32, scaled), rel tables, pwin=0 ----
    #pragma unroll
    for (int i = 0; i < 8; i++) {
        int d = (tid >> 4) + i * 8;
        int l = (tid & 15) * 4;
        float4 qv = *(const float4*)&qp[(size_t)d * LL + l0 + l];
        qs[(l+0)*73 + d] = __uint_as_float(f2tf(qv.x * SCALEC));
        qs[(l+1)*73 + d] = __uint_as_float(f2tf(qv.y * SCALEC));
        qs[(l+2)*73 + d] = __uint_as_float(f2tf(qv.z * SCALEC));
        qs[(l+3)*73 + d] = __uint_as_float(f2tf(qv.w * SCALEC));
    }
    for (int i = tid; i < 9 * 64; i += 128) { rks[i] = relk[i]; rvs[i] = relv[i]; }
    for (int i = tid; i < 64 * 12; i += 128) pwin[i] = 0.f;
    __syncthreads();

    // relbias[l][df] = q_scaled[l] . rel_k[df]
    for (int i = tid; i < 64 * 9; i += 128) {
        int l = i / 9, df = i % 9;
        const float* qq = &qs[l * 73];
        const float* rr = &rks[df * 64];
        float a = 0.f;
        #pragma unroll 16
        for (int d = 0; d < DD; d++) a = fmaf(qq[d], rr[d], a);
        relb[l * 12 + df] = a;
    }

    // per-warp row assignment
    const int r0 = warp * 16 + (lane >> 2);
    const int r1 = r0 + 8;
    const int lk = lane & 3, lm = lane >> 2;
    const float rmask0 = mp[l0 + r0], rmask1 = mp[l0 + r1];

    float co[8][4];
    #pragma unroll
    for (int nt = 0; nt < 8; nt++)
        #pragma unroll
        for (int j = 0; j < 4; j++) co[nt][j] = 0.f;
    float mi0 = -1e30f, mi1 = -1e30f, li0 = 0.f, li1 = 0.f;

    __syncthreads();

    for (int t = 0; t < LL / 64; t++) {
        const int m0 = t * 64;
        // ---- load K (transposed [m][d]) and V (native [d][m]) as tf32 ----
        #pragma unroll
        for (int i = 0; i < 8; i++) {
            int d = (tid >> 4) + i * 8;
            int m = (tid & 15) * 4;
            float4 kv4 = *(const float4*)&kp[(size_t)d * LL + m0 + m];
            ks_[(m+0)*73 + d] = __uint_as_float(f2tf(kv4.x));
            ks_[(m+1)*73 + d] = __uint_as_float(f2tf(kv4.y));
            ks_[(m+2)*73 + d] = __uint_as_float(f2tf(kv4.z));
            ks_[(m+3)*73 + d] = __uint_as_float(f2tf(kv4.w));
            float4 vv4 = *(const float4*)&vp[(size_t)d * LL + m0 + m];
            float4 tv;
            tv.x = __uint_as_float(f2tf(vv4.x));
            tv.y = __uint_as_float(f2tf(vv4.y));
            tv.z = __uint_as_float(f2tf(vv4.z));
            tv.w = __uint_as_float(f2tf(vv4.w));
            *(float4*)&vs[d * 76 + m] = tv;
        }
        if (tid < 64) msks[tid] = mp[m0 + tid];
        __syncthreads();

        // ---- S = Q K^T via mma ----
        float s[8][4];
        #pragma unroll
        for (int nt = 0; nt < 8; nt++)
            #pragma unroll
            for (int j = 0; j < 4; j++) s[nt][j] = 0.f;

        #pragma unroll
        for (int ks8 = 0; ks8 < 64; ks8 += 8) {
            uint32_t a[4];
            a[0] = __float_as_uint(qs[r0*73 + ks8 + lk]);
            a[1] = __float_as_uint(qs[r1*73 + ks8 + lk]);
            a[2] = __float_as_uint(qs[r0*73 + ks8 + lk + 4]);
            a[3] = __float_as_uint(qs[r1*73 + ks8 + lk + 4]);
            #pragma unroll
            for (int nt = 0; nt < 8; nt++) {
                uint32_t bfr[2];
                bfr[0] = __float_as_uint(ks_[(nt*8 + lm)*73 + ks8 + lk]);
                bfr[1] = __float_as_uint(ks_[(nt*8 + lm)*73 + ks8 + lk + 4]);
                mma_tf32(s[nt], a, bfr);
            }
        }

        // ---- rel_k bias + mask ----
        const int gl0 = l0 + r0, gl1 = l0 + r1;
        #pragma unroll
        for (int nt = 0; nt < 8; nt++) {
            #pragma unroll
            for (int j = 0; j < 2; j++) {
                int col = nt*8 + 2*lk + j;
                int gm = m0 + col;
                float cm = msks[col];
                int df0 = gm - gl0;
                if (df0 >= -WW && df0 <= WW) s[nt][j] += relb[r0*12 + df0 + WW];
                if (rmask0 * cm == 0.f) s[nt][j] = -1e4f;
                int df1 = gm - gl1;
                if (df1 >= -WW && df1 <= WW) s[nt][2+j] += relb[r1*12 + df1 + WW];
                if (rmask1 * cm == 0.f) s[nt][2+j] = -1e4f;
            }
        }

        // ---- online softmax ----
        float mx0 = -1e30f, mx1 = -1e30f;
        #pragma unroll
        for (int nt = 0; nt < 8; nt++) {
            mx0 = fmaxf(mx0, fmaxf(s[nt][0], s[nt][1]));
            mx1 = fmaxf(mx1, fmaxf(s[nt][2], s[nt][3]));
        }
        mx0 = fmaxf(mx0, __shfl_xor_sync(0xffffffffu, mx0, 1));
        mx0 = fmaxf(mx0, __shfl_xor_sync(0xffffffffu, mx0, 2));
        mx1 = fmaxf(mx1, __shfl_xor_sync(0xffffffffu, mx1, 1));
        mx1 = fmaxf(mx1, __shfl_xor_sync(0xffffffffu, mx1, 2));

        float nm0 = fmaxf(mi0, mx0), nm1 = fmaxf(mi1, mx1);
        float corr0 = __expf(mi0 - nm0), corr1 = __expf(mi1 - nm1);
        mi0 = nm0; mi1 = nm1;

        float sum0 = 0.f, sum1 = 0.f;
        #pragma unroll
        for (int nt = 0; nt < 8; nt++) {
            s[nt][0] = __expf(s[nt][0] - nm0); s[nt][1] = __expf(s[nt][1] - nm0);
            s[nt][2] = __expf(s[nt][2] - nm1); s[nt][3] = __expf(s[nt][3] - nm1);
            sum0 += s[nt][0] + s[nt][1];
            sum1 += s[nt][2] + s[nt][3];
        }
        sum0 += __shfl_xor_sync(0xffffffffu, sum0, 1);
        sum0 += __shfl_xor_sync(0xffffffffu, sum0, 2);
        sum1 += __shfl_xor_sync(0xffffffffu, sum1, 1);
        sum1 += __shfl_xor_sync(0xffffffffu, sum1, 2);
        li0 = li0 * corr0 + sum0;
        li1 = li1 * corr1 + sum1;

        // rescale O accumulators
        #pragma unroll
        for (int nt = 0; nt < 8; nt++) {
            co[nt][0] *= corr0; co[nt][1] *= corr0;
            co[nt][2] *= corr1; co[nt][3] *= corr1;
        }

        // rescale window probs (one lane per row), then record new ones
        if (lk == 0) {
            #pragma unroll
            for (int j = 0; j < 9; j++) { pwin[r0*12 + j] *= corr0; pwin[r1*12 + j] *= corr1; }
        }
        __syncwarp();
        #pragma unroll
        for (int nt = 0; nt < 8; nt++) {
            #pragma unroll
            for (int j = 0; j < 2; j++) {
                int gm = m0 + nt*8 + 2*lk + j;
                int df0 = gm - gl0;
                if (df0 >= -WW && df0 <= WW) pwin[r0*12 + df0 + WW] = s[nt][j];
                int df1 = gm - gl1;
                if (df1 >= -WW && df1 <= WW) pwin[r1*12 + df1 + WW] = s[nt][2+j];
            }
        }

        // store P tile (own warp rows only) as tf32
        #pragma unroll
        for (int nt = 0; nt < 8; nt++) {
            int c = nt*8 + 2*lk;
            ps[r0*73 + c    ] = __uint_as_float(f2tf(s[nt][0]));
            ps[r0*73 + c + 1] = __uint_as_float(f2tf(s[nt][1]));
            ps[r1*73 + c    ] = __uint_as_float(f2tf(s[nt][2]));
            ps[r1*73 + c + 1] = __uint_as_float(f2tf(s[nt][3]));
        }
        __syncwarp();

        // ---- O += P V via mma ----
        #pragma unroll
        for (int ks8 = 0; ks8 < 64; ks8 += 8) {
            uint32_t a[4];
            a[0] = __float_as_uint(ps[r0*73 + ks8 + lk]);
            a[1] = __float_as_uint(ps[r1*73 + ks8 + lk]);
            a[2] = __float_as_uint(ps[r0*73 + ks8 + lk + 4]);
            a[3] = __float_as_uint(ps[r1*73 + ks8 + lk + 4]);
            #pragma unroll
            for (int nt = 0; nt < 8; nt++) {
                uint32_t bfr[2];
                bfr[0] = __float_as_uint(vs[(nt*8 + lm)*76 + ks8 + lk]);
                bfr[1] = __float_as_uint(vs[(nt*8 + lm)*76 + ks8 + lk + 4]);
                mma_tf32(co[nt], a, bfr);
            }
        }
        __syncthreads();
    }

    // ---- epilogue: normalize, stash [l][d] in ps, add rel_v term, store ----
    float inv0 = 1.0f / li0, inv1 = 1.0f / li1;
    if (lk == 0) { invli[r0] = inv0; invli[r1] = inv1; }
    #pragma unroll
    for (int nt = 0; nt < 8; nt++) {
        int c = nt*8 + 2*lk;
        ps[r0*73 + c    ] = co[nt][0] * inv0;
        ps[r0*73 + c + 1] = co[nt][1] * inv0;
        ps[r1*73 + c    ] = co[nt][2] * inv1;
        ps[r1*73 + c + 1] = co[nt][3] * inv1;
    }
    __syncthreads();

    float* op = O + ((size_t)b * CC + h * DD) * LL;
    #pragma unroll
    for (int i = 0; i < 32; i++) {
        int idx = i * 128 + tid;
        int l = idx & 63;
        int d = idx >> 6;
        float r = 0.f;
        #pragma unroll
        for (int df = 0; df < 9; df++) r = fmaf(pwin[l*12 + df], rvs[df*64 + d], r);
        op[(size_t)d * LL + l0 + l] = ps[l*73 + d] + invli[l] * r;
    }
}

// ---------------- fused residual add + LayerNorm over channels ------------------
__global__ void add_ln_kernel(const float* __restrict__ X, const float* __restrict__ Dl,
                              const float* __restrict__ gam, const float* __restrict__ bet,
                              float* __restrict__ Yo)
{
    int b = blockIdx.y;
    int l = blockIdx.x * 32 + threadIdx.x;
    int cg = threadIdx.y;
    const size_t base = (size_t)b * CC * LL + l;

    float s = 0.f, s2 = 0.f;
    for (int c = cg; c < CC; c += 8) {
        float v = X[base + (size_t)c * LL] + Dl[base + (size_t)c * LL];
        s += v; s2 += v * v;
    }
    __shared__ float sm[8][33], sq[8][33];
    sm[cg][threadIdx.x] = s; sq[cg][threadIdx.x] = s2;
    __syncthreads();
    float ts = 0.f, ts2 = 0.f;
    #pragma unroll
    for (int i = 0; i < 8; i++) { ts += sm[i][threadIdx.x]; ts2 += sq[i][threadIdx.x]; }
    float mean = ts * (1.0f / CC);
    float var  = ts2 * (1.0f / CC) - mean * mean;
    float rstd = rsqrtf(var + EPSC);
    for (int c = cg; c < CC; c += 8) {
        float v = X[base + (size_t)c * LL] + Dl[base + (size_t)c * LL];
        Yo[base + (size_t)c * LL] = (v - mean) * rstd * gam[c] + bet[c];
    }
}

// ---------------- host orchestration -------------------------------------------
extern "C" void kernel_launch(void* const* d_in, const int* in_sizes, int n_in,
                              void* d_out, int out_size)
{
    const float* x    = (const float*)d_in[0];
    const float* mask = (const float*)d_in[1];
    const float* wq = (const float*)d_in[2];  const float* bq = (const float*)d_in[3];
    const float* wk = (const float*)d_in[4];  const float* bk = (const float*)d_in[5];
    const float* wv = (const float*)d_in[6];  const float* bv = (const float*)d_in[7];
    const float* wo = (const float*)d_in[8];  const float* bo = (const float*)d_in[9];
    const float* relk = (const float*)d_in[10];
    const float* relv = (const float*)d_in[11];
    const float* ln1g = (const float*)d_in[12]; const float* ln1b = (const float*)d_in[13];
    const float* w1 = (const float*)d_in[14]; const float* b1 = (const float*)d_in[15];
    const float* w2 = (const float*)d_in[16]; const float* b2 = (const float*)d_in[17];
    const float* ln2g = (const float*)d_in[18]; const float* ln2b = (const float*)d_in[19];

    float *px, *pq, *pk, *pv, *pa, *pt, *ph;
    cudaGetSymbolAddress((void**)&px, g_x);
    cudaGetSymbolAddress((void**)&pq, g_q);
    cudaGetSymbolAddress((void**)&pk, g_k);
    cudaGetSymbolAddress((void**)&pv, g_v);
    cudaGetSymbolAddress((void**)&pa, g_a);
    cudaGetSymbolAddress((void**)&pt, g_t);
    cudaGetSymbolAddress((void**)&ph, g_h);

    const size_t attn_smem = (size_t)(64*73*3 + 64*76 + 9*64*2 + 64*12*2 + 64 + 64) * sizeof(float);
    cudaFuncSetAttribute(attn_tc_kernel, cudaFuncAttributeMaxDynamicSharedMemorySize, (int)attn_smem);

    const int nElem = BB * CC * LL;
    maskmul_kernel<<<nElem / 256, 256>>>(x, mask, px);

    dim3 gQKV(LL / 128, CC / 128, 3 * BB);
    dim3 gP(LL / 128, CC / 128, BB);
    dim3 gF1(LL / 128, FCC / 128, BB);
    dim3 gAttn(LL / 64, HH, BB);
    dim3 gLN(LL / 32, BB);
    dim3 bLN(32, 8);

    for (int i = 0; i < NLL; i++) {
        const float* Wq = wq + (size_t)i * CC * CC;
        const float* Wk = wk + (size_t)i * CC * CC;
        const float* Wv = wv + (size_t)i * CC * CC;
        const float* Wo = wo + (size_t)i * CC * CC;
        const float* W1 = w1 + (size_t)i * FCC * CC;
        const float* W2 = w2 + (size_t)i * CC * FCC;

        gemm_tc_kernel<<<gQKV, 128>>>(Wq, Wk, Wv, bq + i*CC, bk + i*CC, bv + i*CC,
                                      px, mask, pq, pk, pv, CC, LL, CC, 0);

        attn_tc_kernel<<<gAttn, 128, attn_smem>>>(pq, pk, pv, mask,
                                                  relk + (size_t)i * 9 * DD,
                                                  relv + (size_t)i * 9 * DD, pa);

        gemm_tc_kernel<<<gP, 128>>>(Wo, Wo, Wo, bo + i*CC, bo + i*CC, bo + i*CC,
                                    pa, mask, pt, pt, pt, CC, LL, CC, 0);
        add_ln_kernel<<<gLN, bLN>>>(px, pt, ln1g + i*CC, ln1b + i*CC, px);

        gemm_tc_kernel<<<gF1, 128>>>(W1, W1, W1, b1 + i*FCC, b1 + i*FCC, b1 + i*FCC,
                                     px, mask, ph, ph, ph, FCC, LL, CC, 1 | 2 | 4);
        gemm_tc_kernel<<<gP, 128>>>(W2, W2, W2, b2 + i*CC, b2 + i*CC, b2 + i*CC,
                                    ph, mask, pt, pt, pt, CC, LL, FCC, 4);
        add_ln_kernel<<<gLN, bLN>>>(px, pt, ln2g + i*CC, ln2b + i*CC, px);
    }

    maskmul_kernel<<<nElem / 256, 256>>>(px, mask, (float*)d_out);
}

// round 5
// speedup vs baseline: 3.3393x; 1.2084x over previous
#include <cuda_runtime.h>
#include <stdint.h>

#define BB  4
#define CC  512
#define LL  1024
#define HH  8
#define DD  64
#define FCC 2048
#define NLL 4
#define WW  4
#define EPSC 1e-6f
#define SCALEC 0.125f   // 64^-0.5

// ---------------- scratch (static device memory; no allocations) ----------------
__device__ float g_x[BB*CC*LL];
__device__ float g_q[BB*CC*LL];
__device__ float g_k[BB*CC*LL];
__device__ float g_v[BB*CC*LL];
__device__ float g_a[BB*CC*LL];
__device__ float g_t[BB*CC*LL];
__device__ float g_h[(size_t)BB*FCC*LL];

// ---------------- elementwise ----------------------------------------------------
__global__ void maskmul_kernel(const float* __restrict__ X, const float* __restrict__ msk,
                               float* __restrict__ Y) {
    int i = blockIdx.x * 256 + threadIdx.x;
    int l = i & (LL - 1);
    int b = i / (CC * LL);
    Y[i] = X[i] * msk[b * LL + l];
}

// ---------------- tf32 helpers ---------------------------------------------------
__device__ __forceinline__ uint32_t f2tf(float x) {
    uint32_t t;
    asm volatile("cvt.rna.tf32.f32 %0, %1;" : "=r"(t) : "f"(x));
    return t;
}

__device__ __forceinline__ void mma_tf32(float* c, const uint32_t* a, const uint32_t* b) {
    asm volatile(
        "mma.sync.aligned.m16n8k8.row.col.f32.tf32.tf32.f32 "
        "{%0,%1,%2,%3}, {%4,%5,%6,%7}, {%8,%9}, {%0,%1,%2,%3};\n"
        : "+f"(c[0]), "+f"(c[1]), "+f"(c[2]), "+f"(c[3])
        : "r"(a[0]), "r"(a[1]), "r"(a[2]), "r"(a[3]), "r"(b[0]), "r"(b[1]));
}

__device__ __forceinline__ void cpa16(uint32_t s, const float* g) {
    asm volatile("cp.async.cg.shared.global [%0], [%1], 16;" :: "r"(s), "l"(g));
}

// ---------------- tf32 tensor-core GEMM v2: 256 thr, cp.async double buffer ------
// Y[b] = W[M,K] @ X[b][K,N] + bias ; flags: 2=relu, 4=mask out cols
// blockIdx.z selects (mat = z/BB in {W0,W1p,W2p}, b = z%BB) for QKV fusion.
// Block tile 128x128, warp tile 64x32 (warps 2M x 4N), k-step 16.
#define APAD 20
#define BPAD 136
__global__ __launch_bounds__(256, 2) void gemm_tc_kernel(
    const float* __restrict__ W0, const float* __restrict__ W1p, const float* __restrict__ W2p,
    const float* __restrict__ c0, const float* __restrict__ c1, const float* __restrict__ c2,
    const float* __restrict__ X, const float* __restrict__ msk,
    float* __restrict__ Y0, float* __restrict__ Y1p, float* __restrict__ Y2p,
    int M, int N, int K, int flags)
{
    __shared__ float As[2][128 * APAD];   // [m][k] pad 20
    __shared__ float Bs[2][16 * BPAD];    // [k][n] pad 136

    const int tid  = threadIdx.x;
    const int mat  = blockIdx.z / BB;
    const int b    = blockIdx.z % BB;
    const float* Wm   = (mat == 0) ? W0 : (mat == 1 ? W1p : W2p);
    const float* bias = (mat == 0) ? c0 : (mat == 1 ? c1 : c2);
    float*       Y    = (mat == 0) ? Y0 : (mat == 1 ? Y1p : Y2p);

    const int bm = blockIdx.y * 128, bn = blockIdx.x * 128;
    const float* mp = msk + (size_t)b * LL;

    const float* Ag = Wm + (size_t)bm * K;
    const float* Bg = X + (size_t)b * K * N + bn;

    // cp.async chunk assignment (each thread: 2 A chunks, 2 B chunks of 16B)
    const int ar  = tid >> 2;            // A row 0..63 (and +64)
    const int akc = (tid & 3) * 4;       // A k offset
    const int bkk = tid >> 5;            // B k row 0..7 (and +8)
    const int bn4 = (tid & 31) * 4;      // B n offset

    const uint32_t sA = (uint32_t)__cvta_generic_to_shared(&As[0][0]);
    const uint32_t sB = (uint32_t)__cvta_generic_to_shared(&Bs[0][0]);

    #define ISSUE(ST, K0) do { \
        cpa16(sA + (uint32_t)(((ST) * 128 * APAD) + ar * APAD + akc) * 4, \
              Ag + (size_t)ar * K + (K0) + akc); \
        cpa16(sA + (uint32_t)(((ST) * 128 * APAD) + (ar + 64) * APAD + akc) * 4, \
              Ag + (size_t)(ar + 64) * K + (K0) + akc); \
        cpa16(sB + (uint32_t)(((ST) * 16 * BPAD) + bkk * BPAD + bn4) * 4, \
              Bg + (size_t)((K0) + bkk) * N + bn4); \
        cpa16(sB + (uint32_t)(((ST) * 16 * BPAD) + (bkk + 8) * BPAD + bn4) * 4, \
              Bg + (size_t)((K0) + bkk + 8) * N + bn4); \
        asm volatile("cp.async.commit_group;" ::: "memory"); \
    } while (0)

    const int lane = tid & 31, warp = tid >> 5;
    const int wm = (warp >> 2) * 64;     // 2 warp rows
    const int wn = (warp & 3) * 32;      // 4 warp cols
    const int lm = lane >> 2, lk = lane & 3;

    float acc[4][4][4];
    #pragma unroll
    for (int i = 0; i < 4; i++)
        #pragma unroll
        for (int j = 0; j < 4; j++)
            #pragma unroll
            for (int r = 0; r < 4; r++) acc[i][j][r] = 0.f;

    const int nIter = K / 16;
    ISSUE(0, 0);
    if (nIter > 1) ISSUE(1, 16);

    for (int it = 0; it < nIter; it++) {
        if (it + 1 < nIter) asm volatile("cp.async.wait_group 1;" ::: "memory");
        else                asm volatile("cp.async.wait_group 0;" ::: "memory");
        __syncthreads();

        const int buf = it & 1;
        const float* Ab = As[buf];
        const float* Bbp = Bs[buf];
        #pragma unroll
        for (int ks = 0; ks < 16; ks += 8) {
            uint32_t a[4][4], bfr[4][2];
            #pragma unroll
            for (int mt = 0; mt < 4; mt++) {
                a[mt][0] = f2tf(Ab[(wm + mt*16 + lm    ) * APAD + ks + lk    ]);
                a[mt][1] = f2tf(Ab[(wm + mt*16 + lm + 8) * APAD + ks + lk    ]);
                a[mt][2] = f2tf(Ab[(wm + mt*16 + lm    ) * APAD + ks + lk + 4]);
                a[mt][3] = f2tf(Ab[(wm + mt*16 + lm + 8) * APAD + ks + lk + 4]);
            }
            #pragma unroll
            for (int nt = 0; nt < 4; nt++) {
                bfr[nt][0] = f2tf(Bbp[(ks + lk    ) * BPAD + wn + nt*8 + lm]);
                bfr[nt][1] = f2tf(Bbp[(ks + lk + 4) * BPAD + wn + nt*8 + lm]);
            }
            #pragma unroll
            for (int mt = 0; mt < 4; mt++)
                #pragma unroll
                for (int nt = 0; nt < 4; nt++)
                    mma_tf32(acc[mt][nt], a[mt], bfr[nt]);
        }
        __syncthreads();
        if (it + 2 < nIter) ISSUE(buf, (it + 2) * 16);
    }
    #undef ISSUE

    // ---------------- epilogue ----------------
    const bool relu = flags & 2;
    const bool omask = flags & 4;
    float* Yb = Y + (size_t)b * M * N;
    #pragma unroll
    for (int mt = 0; mt < 4; mt++) {
        #pragma unroll
        for (int half = 0; half < 2; half++) {
            int m = bm + wm + mt * 16 + lm + half * 8;
            float bv = bias[m];
            #pragma unroll
            for (int nt = 0; nt < 4; nt++) {
                int n = bn + wn + nt * 8 + lk * 2;
                float v0 = acc[mt][nt][half * 2 + 0] + bv;
                float v1 = acc[mt][nt][half * 2 + 1] + bv;
                if (relu) { v0 = fmaxf(v0, 0.f); v1 = fmaxf(v1, 0.f); }
                if (omask) { v0 *= mp[n]; v1 *= mp[n + 1]; }
                *(float2*)&Yb[(size_t)m * N + n] = make_float2(v0, v1);
            }
        }
    }
}

// ---------------- tensor-core flash attention (unchanged from R4) ----------------
__global__ __launch_bounds__(128) void attn_tc_kernel(
    const float* __restrict__ Q, const float* __restrict__ Kk,
    const float* __restrict__ V, const float* __restrict__ msk,
    const float* __restrict__ relk, const float* __restrict__ relv,
    float* __restrict__ O)
{
    extern __shared__ float smem[];
    float* qs    = smem;                 // [64][73]
    float* ks_   = qs    + 64 * 73;      // [64][73]
    float* ps    = ks_   + 64 * 73;      // [64][73]
    float* vs    = ps    + 64 * 73;      // [64][76]
    float* rks   = vs    + 64 * 76;      // [9][64]
    float* rvs   = rks   + 9 * 64;       // [9][64]
    float* relb  = rvs   + 9 * 64;       // [64][12]
    float* pwin  = relb  + 64 * 12;      // [64][12]
    float* invli = pwin  + 64 * 12;      // [64]
    float* msks  = invli + 64;           // [64]

    const int tid = threadIdx.x;
    const int lane = tid & 31, warp = tid >> 5;
    const int b = blockIdx.z, h = blockIdx.y;
    const int l0 = blockIdx.x * 64;

    const float* qp = Q  + ((size_t)b * CC + h * DD) * LL;
    const float* kp = Kk + ((size_t)b * CC + h * DD) * LL;
    const float* vp = V  + ((size_t)b * CC + h * DD) * LL;
    const float* mp = msk + (size_t)b * LL;

    #pragma unroll
    for (int i = 0; i < 8; i++) {
        int d = (tid >> 4) + i * 8;
        int l = (tid & 15) * 4;
        float4 qv = *(const float4*)&qp[(size_t)d * LL + l0 + l];
        qs[(l+0)*73 + d] = __uint_as_float(f2tf(qv.x * SCALEC));
        qs[(l+1)*73 + d] = __uint_as_float(f2tf(qv.y * SCALEC));
        qs[(l+2)*73 + d] = __uint_as_float(f2tf(qv.z * SCALEC));
        qs[(l+3)*73 + d] = __uint_as_float(f2tf(qv.w * SCALEC));
    }
    for (int i = tid; i < 9 * 64; i += 128) { rks[i] = relk[i]; rvs[i] = relv[i]; }
    for (int i = tid; i < 64 * 12; i += 128) pwin[i] = 0.f;
    __syncthreads();

    for (int i = tid; i < 64 * 9; i += 128) {
        int l = i / 9, df = i % 9;
        const float* qq = &qs[l * 73];
        const float* rr = &rks[df * 64];
        float a = 0.f;
        #pragma unroll 16
        for (int d = 0; d < DD; d++) a = fmaf(qq[d], rr[d], a);
        relb[l * 12 + df] = a;
    }

    const int r0 = warp * 16 + (lane >> 2);
    const int r1 = r0 + 8;
    const int lk = lane & 3, lm = lane >> 2;
    const float rmask0 = mp[l0 + r0], rmask1 = mp[l0 + r1];

    float co[8][4];
    #pragma unroll
    for (int nt = 0; nt < 8; nt++)
        #pragma unroll
        for (int j = 0; j < 4; j++) co[nt][j] = 0.f;
    float mi0 = -1e30f, mi1 = -1e30f, li0 = 0.f, li1 = 0.f;

    __syncthreads();

    for (int t = 0; t < LL / 64; t++) {
        const int m0 = t * 64;
        #pragma unroll
        for (int i = 0; i < 8; i++) {
            int d = (tid >> 4) + i * 8;
            int m = (tid & 15) * 4;
            float4 kv4 = *(const float4*)&kp[(size_t)d * LL + m0 + m];
            ks_[(m+0)*73 + d] = __uint_as_float(f2tf(kv4.x));
            ks_[(m+1)*73 + d] = __uint_as_float(f2tf(kv4.y));
            ks_[(m+2)*73 + d] = __uint_as_float(f2tf(kv4.z));
            ks_[(m+3)*73 + d] = __uint_as_float(f2tf(kv4.w));
            float4 vv4 = *(const float4*)&vp[(size_t)d * LL + m0 + m];
            float4 tv;
            tv.x = __uint_as_float(f2tf(vv4.x));
            tv.y = __uint_as_float(f2tf(vv4.y));
            tv.z = __uint_as_float(f2tf(vv4.z));
            tv.w = __uint_as_float(f2tf(vv4.w));
            *(float4*)&vs[d * 76 + m] = tv;
        }
        if (tid < 64) msks[tid] = mp[m0 + tid];
        __syncthreads();

        float s[8][4];
        #pragma unroll
        for (int nt = 0; nt < 8; nt++)
            #pragma unroll
            for (int j = 0; j < 4; j++) s[nt][j] = 0.f;

        #pragma unroll
        for (int ks8 = 0; ks8 < 64; ks8 += 8) {
            uint32_t a[4];
            a[0] = __float_as_uint(qs[r0*73 + ks8 + lk]);
            a[1] = __float_as_uint(qs[r1*73 + ks8 + lk]);
            a[2] = __float_as_uint(qs[r0*73 + ks8 + lk + 4]);
            a[3] = __float_as_uint(qs[r1*73 + ks8 + lk + 4]);
            #pragma unroll
            for (int nt = 0; nt < 8; nt++) {
                uint32_t bfr[2];
                bfr[0] = __float_as_uint(ks_[(nt*8 + lm)*73 + ks8 + lk]);
                bfr[1] = __float_as_uint(ks_[(nt*8 + lm)*73 + ks8 + lk + 4]);
                mma_tf32(s[nt], a, bfr);
            }
        }

        const int gl0 = l0 + r0, gl1 = l0 + r1;
        #pragma unroll
        for (int nt = 0; nt < 8; nt++) {
            #pragma unroll
            for (int j = 0; j < 2; j++) {
                int col = nt*8 + 2*lk + j;
                int gm = m0 + col;
                float cm = msks[col];
                int df0 = gm - gl0;
                if (df0 >= -WW && df0 <= WW) s[nt][j] += relb[r0*12 + df0 + WW];
                if (rmask0 * cm == 0.f) s[nt][j] = -1e4f;
                int df1 = gm - gl1;
                if (df1 >= -WW && df1 <= WW) s[nt][2+j] += relb[r1*12 + df1 + WW];
                if (rmask1 * cm == 0.f) s[nt][2+j] = -1e4f;
            }
        }

        float mx0 = -1e30f, mx1 = -1e30f;
        #pragma unroll
        for (int nt = 0; nt < 8; nt++) {
            mx0 = fmaxf(mx0, fmaxf(s[nt][0], s[nt][1]));
            mx1 = fmaxf(mx1, fmaxf(s[nt][2], s[nt][3]));
        }
        mx0 = fmaxf(mx0, __shfl_xor_sync(0xffffffffu, mx0, 1));
        mx0 = fmaxf(mx0, __shfl_xor_sync(0xffffffffu, mx0, 2));
        mx1 = fmaxf(mx1, __shfl_xor_sync(0xffffffffu, mx1, 1));
        mx1 = fmaxf(mx1, __shfl_xor_sync(0xffffffffu, mx1, 2));

        float nm0 = fmaxf(mi0, mx0), nm1 = fmaxf(mi1, mx1);
        float corr0 = __expf(mi0 - nm0), corr1 = __expf(mi1 - nm1);
        mi0 = nm0; mi1 = nm1;

        float sum0 = 0.f, sum1 = 0.f;
        #pragma unroll
        for (int nt = 0; nt < 8; nt++) {
            s[nt][0] = __expf(s[nt][0] - nm0); s[nt][1] = __expf(s[nt][1] - nm0);
            s[nt][2] = __expf(s[nt][2] - nm1); s[nt][3] = __expf(s[nt][3] - nm1);
            sum0 += s[nt][0] + s[nt][1];
            sum1 += s[nt][2] + s[nt][3];
        }
        sum0 += __shfl_xor_sync(0xffffffffu, sum0, 1);
        sum0 += __shfl_xor_sync(0xffffffffu, sum0, 2);
        sum1 += __shfl_xor_sync(0xffffffffu, sum1, 1);
        sum1 += __shfl_xor_sync(0xffffffffu, sum1, 2);
        li0 = li0 * corr0 + sum0;
        li1 = li1 * corr1 + sum1;

        #pragma unroll
        for (int nt = 0; nt < 8; nt++) {
            co[nt][0] *= corr0; co[nt][1] *= corr0;
            co[nt][2] *= corr1; co[nt][3] *= corr1;
        }

        if (lk == 0) {
            #pragma unroll
            for (int j = 0; j < 9; j++) { pwin[r0*12 + j] *= corr0; pwin[r1*12 + j] *= corr1; }
        }
        __syncwarp();
        #pragma unroll
        for (int nt = 0; nt < 8; nt++) {
            #pragma unroll
            for (int j = 0; j < 2; j++) {
                int gm = m0 + nt*8 + 2*lk + j;
                int df0 = gm - gl0;
                if (df0 >= -WW && df0 <= WW) pwin[r0*12 + df0 + WW] = s[nt][j];
                int df1 = gm - gl1;
                if (df1 >= -WW && df1 <= WW) pwin[r1*12 + df1 + WW] = s[nt][2+j];
            }
        }

        #pragma unroll
        for (int nt = 0; nt < 8; nt++) {
            int c = nt*8 + 2*lk;
            ps[r0*73 + c    ] = __uint_as_float(f2tf(s[nt][0]));
            ps[r0*73 + c + 1] = __uint_as_float(f2tf(s[nt][1]));
            ps[r1*73 + c    ] = __uint_as_float(f2tf(s[nt][2]));
            ps[r1*73 + c + 1] = __uint_as_float(f2tf(s[nt][3]));
        }
        __syncwarp();

        #pragma unroll
        for (int ks8 = 0; ks8 < 64; ks8 += 8) {
            uint32_t a[4];
            a[0] = __float_as_uint(ps[r0*73 + ks8 + lk]);
            a[1] = __float_as_uint(ps[r1*73 + ks8 + lk]);
            a[2] = __float_as_uint(ps[r0*73 + ks8 + lk + 4]);
            a[3] = __float_as_uint(ps[r1*73 + ks8 + lk + 4]);
            #pragma unroll
            for (int nt = 0; nt < 8; nt++) {
                uint32_t bfr[2];
                bfr[0] = __float_as_uint(vs[(nt*8 + lm)*76 + ks8 + lk]);
                bfr[1] = __float_as_uint(vs[(nt*8 + lm)*76 + ks8 + lk + 4]);
                mma_tf32(co[nt], a, bfr);
            }
        }
        __syncthreads();
    }

    float inv0 = 1.0f / li0, inv1 = 1.0f / li1;
    if (lk == 0) { invli[r0] = inv0; invli[r1] = inv1; }
    #pragma unroll
    for (int nt = 0; nt < 8; nt++) {
        int c = nt*8 + 2*lk;
        ps[r0*73 + c    ] = co[nt][0] * inv0;
        ps[r0*73 + c + 1] = co[nt][1] * inv0;
        ps[r1*73 + c    ] = co[nt][2] * inv1;
        ps[r1*73 + c + 1] = co[nt][3] * inv1;
    }
    __syncthreads();

    float* op = O + ((size_t)b * CC + h * DD) * LL;
    #pragma unroll
    for (int i = 0; i < 32; i++) {
        int idx = i * 128 + tid;
        int l = idx & 63;
        int d = idx >> 6;
        float r = 0.f;
        #pragma unroll
        for (int df = 0; df < 9; df++) r = fmaf(pwin[l*12 + df], rvs[df*64 + d], r);
        op[(size_t)d * LL + l0 + l] = ps[l*73 + d] + invli[l] * r;
    }
}

// ---------------- fused residual add + LayerNorm over channels ------------------
__global__ void add_ln_kernel(const float* __restrict__ X, const float* __restrict__ Dl,
                              const float* __restrict__ gam, const float* __restrict__ bet,
                              float* __restrict__ Yo)
{
    int b = blockIdx.y;
    int l = blockIdx.x * 32 + threadIdx.x;
    int cg = threadIdx.y;
    const size_t base = (size_t)b * CC * LL + l;

    float s = 0.f, s2 = 0.f;
    for (int c = cg; c < CC; c += 8) {
        float v = X[base + (size_t)c * LL] + Dl[base + (size_t)c * LL];
        s += v; s2 += v * v;
    }
    __shared__ float sm[8][33], sq[8][33];
    sm[cg][threadIdx.x] = s; sq[cg][threadIdx.x] = s2;
    __syncthreads();
    float ts = 0.f, ts2 = 0.f;
    #pragma unroll
    for (int i = 0; i < 8; i++) { ts += sm[i][threadIdx.x]; ts2 += sq[i][threadIdx.x]; }
    float mean = ts * (1.0f / CC);
    float var  = ts2 * (1.0f / CC) - mean * mean;
    float rstd = rsqrtf(var + EPSC);
    for (int c = cg; c < CC; c += 8) {
        float v = X[base + (size_t)c * LL] + Dl[base + (size_t)c * LL];
        Yo[base + (size_t)c * LL] = (v - mean) * rstd * gam[c] + bet[c];
    }
}

// ---------------- host orchestration -------------------------------------------
extern "C" void kernel_launch(void* const* d_in, const int* in_sizes, int n_in,
                              void* d_out, int out_size)
{
    const float* x    = (const float*)d_in[0];
    const float* mask = (const float*)d_in[1];
    const float* wq = (const float*)d_in[2];  const float* bq = (const float*)d_in[3];
    const float* wk = (const float*)d_in[4];  const float* bk = (const float*)d_in[5];
    const float* wv = (const float*)d_in[6];  const float* bv = (const float*)d_in[7];
    const float* wo = (const float*)d_in[8];  const float* bo = (const float*)d_in[9];
    const float* relk = (const float*)d_in[10];
    const float* relv = (const float*)d_in[11];
    const float* ln1g = (const float*)d_in[12]; const float* ln1b = (const float*)d_in[13];
    const float* w1 = (const float*)d_in[14]; const float* b1 = (const float*)d_in[15];
    const float* w2 = (const float*)d_in[16]; const float* b2 = (const float*)d_in[17];
    const float* ln2g = (const float*)d_in[18]; const float* ln2b = (const float*)d_in[19];

    float *px, *pq, *pk, *pv, *pa, *pt, *ph;
    cudaGetSymbolAddress((void**)&px, g_x);
    cudaGetSymbolAddress((void**)&pq, g_q);
    cudaGetSymbolAddress((void**)&pk, g_k);
    cudaGetSymbolAddress((void**)&pv, g_v);
    cudaGetSymbolAddress((void**)&pa, g_a);
    cudaGetSymbolAddress((void**)&pt, g_t);
    cudaGetSymbolAddress((void**)&ph, g_h);

    const size_t attn_smem = (size_t)(64*73*3 + 64*76 + 9*64*2 + 64*12*2 + 64 + 64) * sizeof(float);
    cudaFuncSetAttribute(attn_tc_kernel, cudaFuncAttributeMaxDynamicSharedMemorySize, (int)attn_smem);

    const int nElem = BB * CC * LL;
    maskmul_kernel<<<nElem / 256, 256>>>(x, mask, px);

    dim3 gQKV(LL / 128, CC / 128, 3 * BB);
    dim3 gP(LL / 128, CC / 128, BB);
    dim3 gF1(LL / 128, FCC / 128, BB);
    dim3 gAttn(LL / 64, HH, BB);
    dim3 gLN(LL / 32, BB);
    dim3 bLN(32, 8);

    for (int i = 0; i < NLL; i++) {
        const float* Wq = wq + (size_t)i * CC * CC;
        const float* Wk = wk + (size_t)i * CC * CC;
        const float* Wv = wv + (size_t)i * CC * CC;
        const float* Wo = wo + (size_t)i * CC * CC;
        const float* W1 = w1 + (size_t)i * FCC * CC;
        const float* W2 = w2 + (size_t)i * CC * FCC;

        gemm_tc_kernel<<<gQKV, 256>>>(Wq, Wk, Wv, bq + i*CC, bk + i*CC, bv + i*CC,
                                      px, mask, pq, pk, pv, CC, LL, CC, 0);

        attn_tc_kernel<<<gAttn, 128, attn_smem>>>(pq, pk, pv, mask,
                                                  relk + (size_t)i * 9 * DD,
                                                  relv + (size_t)i * 9 * DD, pa);

        gemm_tc_kernel<<<gP, 256>>>(Wo, Wo, Wo, bo + i*CC, bo + i*CC, bo + i*CC,
                                    pa, mask, pt, pt, pt, CC, LL, CC, 0);
        add_ln_kernel<<<gLN, bLN>>>(px, pt, ln1g + i*CC, ln1b + i*CC, px);

        gemm_tc_kernel<<<gF1, 256>>>(W1, W1, W1, b1 + i*FCC, b1 + i*FCC, b1 + i*FCC,
                                     px, mask, ph, ph, ph, FCC, LL, CC, 2 | 4);
        gemm_tc_kernel<<<gP, 256>>>(W2, W2, W2, b2 + i*CC, b2 + i*CC, b2 + i*CC,
                                    ph, mask, pt, pt, pt, CC, LL, FCC, 4);
        add_ln_kernel<<<gLN, bLN>>>(px, pt, ln2g + i*CC, ln2b + i*CC, px);
    }

    maskmul_kernel<<<nElem / 256, 256>>>(px, mask, (float*)d_out);
}

// round 6
// speedup vs baseline: 3.4318x; 1.0277x over previous
#include <cuda_runtime.h>
#include <stdint.h>

#define BB  4
#define CC  512
#define LL  1024
#define HH  8
#define DD  64
#define FCC 2048
#define NLL 4
#define WW  4
#define EPSC 1e-6f
#define SCALEC 0.125f   // 64^-0.5

// ---------------- scratch (static device memory; no allocations) ----------------
__device__ float g_x[BB*CC*LL];
__device__ float g_q[BB*CC*LL];
__device__ float g_k[BB*CC*LL];     // also reused as split-K partial #2
__device__ float g_v[BB*CC*LL];
__device__ float g_a[BB*CC*LL];
__device__ float g_t[BB*CC*LL];
__device__ float g_h[(size_t)BB*FCC*LL];
__device__ float g_zero[CC];        // zero-initialized (bias for split-K part 1)

// ---------------- elementwise ----------------------------------------------------
__global__ void maskmul_kernel(const float* __restrict__ X, const float* __restrict__ msk,
                               float* __restrict__ Y) {
    int i = blockIdx.x * 256 + threadIdx.x;
    int l = i & (LL - 1);
    int b = i / (CC * LL);
    Y[i] = X[i] * msk[b * LL + l];
}

// ---------------- tf32 helpers ---------------------------------------------------
__device__ __forceinline__ uint32_t f2tf(float x) {
    uint32_t t;
    asm volatile("cvt.rna.tf32.f32 %0, %1;" : "=r"(t) : "f"(x));
    return t;
}

__device__ __forceinline__ void mma_tf32(float* c, const uint32_t* a, const uint32_t* b) {
    asm volatile(
        "mma.sync.aligned.m16n8k8.row.col.f32.tf32.tf32.f32 "
        "{%0,%1,%2,%3}, {%4,%5,%6,%7}, {%8,%9}, {%0,%1,%2,%3};\n"
        : "+f"(c[0]), "+f"(c[1]), "+f"(c[2]), "+f"(c[3])
        : "r"(a[0]), "r"(a[1]), "r"(a[2]), "r"(a[3]), "r"(b[0]), "r"(b[1]));
}

__device__ __forceinline__ void cpa16(uint32_t s, const float* g) {
    asm volatile("cp.async.cg.shared.global [%0], [%1], 16;" :: "r"(s), "l"(g));
}

__device__ __forceinline__ void ldm_x4(uint32_t* r, uint32_t a) {
    asm volatile("ldmatrix.sync.aligned.m8n8.x4.shared.b16 {%0,%1,%2,%3}, [%4];"
        : "=r"(r[0]), "=r"(r[1]), "=r"(r[2]), "=r"(r[3]) : "r"(a));
}

// ---------------- tf32 tensor-core GEMM v3 ---------------------------------------
// Y[b] = W[M,K] @ X[b][K,N] + bias
// flags: 2=relu, 4=mask out cols, 8=split-K2 (mat selects k-half; same W)
// blockIdx.z: mat = z/BB (QKV fusion or split half), b = z%BB.
// 256 threads, block tile 128x128, warp 64x32, k-step 16, 3-stage cp.async.
// Raw fp32 fed to tf32 MMA (hardware truncates) — no cvt in the hot loop.
#define APAD 20
#define BPAD 136
#define STG_A (128 * APAD)
#define STG_B (16 * BPAD)
__global__ __launch_bounds__(256, 2) void gemm_tc_kernel(
    const float* __restrict__ W0, const float* __restrict__ W1p, const float* __restrict__ W2p,
    const float* __restrict__ c0, const float* __restrict__ c1, const float* __restrict__ c2,
    const float* __restrict__ X, const float* __restrict__ msk,
    float* __restrict__ Y0, float* __restrict__ Y1p, float* __restrict__ Y2p,
    int M, int N, int K, int flags)
{
    extern __shared__ float gsm[];
    float* As = gsm;               // 3 stages [m][k] pad 20
    float* Bs = gsm + 3 * STG_A;   // 3 stages [k][n] pad 136

    const int tid  = threadIdx.x;
    const int mat  = blockIdx.z / BB;
    const int b    = blockIdx.z % BB;
    const bool splitk = flags & 8;
    const float* Wm   = (mat == 0) ? W0 : (mat == 1 ? W1p : W2p);
    const float* bias = (mat == 0) ? c0 : (mat == 1 ? c1 : c2);
    float*       Y    = (mat == 0) ? Y0 : (mat == 1 ? Y1p : Y2p);

    const int Keff = splitk ? (K >> 1) : K;
    const int kOff = splitk ? mat * Keff : 0;

    const int bm = blockIdx.y * 128, bn = blockIdx.x * 128;
    const float* mp = msk + (size_t)b * LL;

    const float* Ag = Wm + (size_t)bm * K + kOff;
    const float* Bg = X + (size_t)b * K * N + (size_t)kOff * N + bn;

    const int ar  = tid >> 2;
    const int akc = (tid & 3) * 4;
    const int bkk = tid >> 5;
    const int bn4 = (tid & 31) * 4;

    const uint32_t sA = (uint32_t)__cvta_generic_to_shared(As);
    const uint32_t sB = (uint32_t)__cvta_generic_to_shared(Bs);

    #define ISSUE(ST, K0) do { \
        cpa16(sA + (uint32_t)(((ST) * STG_A) + ar * APAD + akc) * 4, \
              Ag + (size_t)ar * K + (K0) + akc); \
        cpa16(sA + (uint32_t)(((ST) * STG_A) + (ar + 64) * APAD + akc) * 4, \
              Ag + (size_t)(ar + 64) * K + (K0) + akc); \
        cpa16(sB + (uint32_t)(((ST) * STG_B) + bkk * BPAD + bn4) * 4, \
              Bg + (size_t)((K0) + bkk) * N + bn4); \
        cpa16(sB + (uint32_t)(((ST) * STG_B) + (bkk + 8) * BPAD + bn4) * 4, \
              Bg + (size_t)((K0) + bkk + 8) * N + bn4); \
        asm volatile("cp.async.commit_group;" ::: "memory"); \
    } while (0)

    const int lane = tid & 31, warp = tid >> 5;
    const int wm = (warp >> 2) * 64;
    const int wn = (warp & 3) * 32;
    const int lm = lane >> 2, lk = lane & 3;
    // ldmatrix per-lane source row/col within the A tile
    const int mrow = (lane & 7) + ((lane >> 3) & 1) * 8;
    const int kadd = (lane >> 4) * 4;

    float acc[4][4][4];
    #pragma unroll
    for (int i = 0; i < 4; i++)
        #pragma unroll
        for (int j = 0; j < 4; j++)
            #pragma unroll
            for (int r = 0; r < 4; r++) acc[i][j][r] = 0.f;

    const int nIter = Keff / 16;
    ISSUE(0, 0);
    ISSUE(1, 16);

    for (int it = 0; it < nIter; it++) {
        if (it + 2 < nIter) ISSUE((it + 2) % 3, (it + 2) * 16);
        else asm volatile("cp.async.commit_group;" ::: "memory");
        asm volatile("cp.async.wait_group 2;" ::: "memory");
        __syncthreads();

        const int buf = it % 3;
        const uint32_t aBase = sA + (uint32_t)(buf * STG_A) * 4;
        const float* Bb = Bs + buf * STG_B;
        #pragma unroll
        for (int ks = 0; ks < 16; ks += 8) {
            uint32_t a[4][4], bfr[4][2];
            #pragma unroll
            for (int mt = 0; mt < 4; mt++)
                ldm_x4(a[mt], aBase + (uint32_t)((wm + mt*16 + mrow) * APAD + ks + kadd) * 4);
            #pragma unroll
            for (int nt = 0; nt < 4; nt++) {
                bfr[nt][0] = __float_as_uint(Bb[(ks + lk    ) * BPAD + wn + nt*8 + lm]);
                bfr[nt][1] = __float_as_uint(Bb[(ks + lk + 4) * BPAD + wn + nt*8 + lm]);
            }
            #pragma unroll
            for (int mt = 0; mt < 4; mt++)
                #pragma unroll
                for (int nt = 0; nt < 4; nt++)
                    mma_tf32(acc[mt][nt], a[mt], bfr[nt]);
        }
        __syncthreads();
    }
    #undef ISSUE

    // ---------------- epilogue ----------------
    const bool relu = flags & 2;
    const bool omask = flags & 4;
    float* Yb = Y + (size_t)b * M * N;
    #pragma unroll
    for (int mt = 0; mt < 4; mt++) {
        #pragma unroll
        for (int half = 0; half < 2; half++) {
            int m = bm + wm + mt * 16 + lm + half * 8;
            float bv = bias[m];
            #pragma unroll
            for (int nt = 0; nt < 4; nt++) {
                int n = bn + wn + nt * 8 + lk * 2;
                float v0 = acc[mt][nt][half * 2 + 0] + bv;
                float v1 = acc[mt][nt][half * 2 + 1] + bv;
                if (relu) { v0 = fmaxf(v0, 0.f); v1 = fmaxf(v1, 0.f); }
                if (omask) { v0 *= mp[n]; v1 *= mp[n + 1]; }
                *(float2*)&Yb[(size_t)m * N + n] = make_float2(v0, v1);
            }
        }
    }
}

// ---------------- tensor-core flash attention (unchanged) ------------------------
__global__ __launch_bounds__(128) void attn_tc_kernel(
    const float* __restrict__ Q, const float* __restrict__ Kk,
    const float* __restrict__ V, const float* __restrict__ msk,
    const float* __restrict__ relk, const float* __restrict__ relv,
    float* __restrict__ O)
{
    extern __shared__ float smem[];
    float* qs    = smem;                 // [64][73]
    float* ks_   = qs    + 64 * 73;      // [64][73]
    float* ps    = ks_   + 64 * 73;      // [64][73]
    float* vs    = ps    + 64 * 73;      // [64][76]
    float* rks   = vs    + 64 * 76;      // [9][64]
    float* rvs   = rks   + 9 * 64;       // [9][64]
    float* relb  = rvs   + 9 * 64;       // [64][12]
    float* pwin  = relb  + 64 * 12;      // [64][12]
    float* invli = pwin  + 64 * 12;      // [64]
    float* msks  = invli + 64;           // [64]

    const int tid = threadIdx.x;
    const int lane = tid & 31, warp = tid >> 5;
    const int b = blockIdx.z, h = blockIdx.y;
    const int l0 = blockIdx.x * 64;

    const float* qp = Q  + ((size_t)b * CC + h * DD) * LL;
    const float* kp = Kk + ((size_t)b * CC + h * DD) * LL;
    const float* vp = V  + ((size_t)b * CC + h * DD) * LL;
    const float* mp = msk + (size_t)b * LL;

    #pragma unroll
    for (int i = 0; i < 8; i++) {
        int d = (tid >> 4) + i * 8;
        int l = (tid & 15) * 4;
        float4 qv = *(const float4*)&qp[(size_t)d * LL + l0 + l];
        qs[(l+0)*73 + d] = __uint_as_float(f2tf(qv.x * SCALEC));
        qs[(l+1)*73 + d] = __uint_as_float(f2tf(qv.y * SCALEC));
        qs[(l+2)*73 + d] = __uint_as_float(f2tf(qv.z * SCALEC));
        qs[(l+3)*73 + d] = __uint_as_float(f2tf(qv.w * SCALEC));
    }
    for (int i = tid; i < 9 * 64; i += 128) { rks[i] = relk[i]; rvs[i] = relv[i]; }
    for (int i = tid; i < 64 * 12; i += 128) pwin[i] = 0.f;
    __syncthreads();

    for (int i = tid; i < 64 * 9; i += 128) {
        int l = i / 9, df = i % 9;
        const float* qq = &qs[l * 73];
        const float* rr = &rks[df * 64];
        float a = 0.f;
        #pragma unroll 16
        for (int d = 0; d < DD; d++) a = fmaf(qq[d], rr[d], a);
        relb[l * 12 + df] = a;
    }

    const int r0 = warp * 16 + (lane >> 2);
    const int r1 = r0 + 8;
    const int lk = lane & 3, lm = lane >> 2;
    const float rmask0 = mp[l0 + r0], rmask1 = mp[l0 + r1];

    float co[8][4];
    #pragma unroll
    for (int nt = 0; nt < 8; nt++)
        #pragma unroll
        for (int j = 0; j < 4; j++) co[nt][j] = 0.f;
    float mi0 = -1e30f, mi1 = -1e30f, li0 = 0.f, li1 = 0.f;

    __syncthreads();

    for (int t = 0; t < LL / 64; t++) {
        const int m0 = t * 64;
        #pragma unroll
        for (int i = 0; i < 8; i++) {
            int d = (tid >> 4) + i * 8;
            int m = (tid & 15) * 4;
            float4 kv4 = *(const float4*)&kp[(size_t)d * LL + m0 + m];
            ks_[(m+0)*73 + d] = __uint_as_float(f2tf(kv4.x));
            ks_[(m+1)*73 + d] = __uint_as_float(f2tf(kv4.y));
            ks_[(m+2)*73 + d] = __uint_as_float(f2tf(kv4.z));
            ks_[(m+3)*73 + d] = __uint_as_float(f2tf(kv4.w));
            float4 vv4 = *(const float4*)&vp[(size_t)d * LL + m0 + m];
            float4 tv;
            tv.x = __uint_as_float(f2tf(vv4.x));
            tv.y = __uint_as_float(f2tf(vv4.y));
            tv.z = __uint_as_float(f2tf(vv4.z));
            tv.w = __uint_as_float(f2tf(vv4.w));
            *(float4*)&vs[d * 76 + m] = tv;
        }
        if (tid < 64) msks[tid] = mp[m0 + tid];
        __syncthreads();

        float s[8][4];
        #pragma unroll
        for (int nt = 0; nt < 8; nt++)
            #pragma unroll
            for (int j = 0; j < 4; j++) s[nt][j] = 0.f;

        #pragma unroll
        for (int ks8 = 0; ks8 < 64; ks8 += 8) {
            uint32_t a[4];
            a[0] = __float_as_uint(qs[r0*73 + ks8 + lk]);
            a[1] = __float_as_uint(qs[r1*73 + ks8 + lk]);
            a[2] = __float_as_uint(qs[r0*73 + ks8 + lk + 4]);
            a[3] = __float_as_uint(qs[r1*73 + ks8 + lk + 4]);
            #pragma unroll
            for (int nt = 0; nt < 8; nt++) {
                uint32_t bfr[2];
                bfr[0] = __float_as_uint(ks_[(nt*8 + lm)*73 + ks8 + lk]);
                bfr[1] = __float_as_uint(ks_[(nt*8 + lm)*73 + ks8 + lk + 4]);
                mma_tf32(s[nt], a, bfr);
            }
        }

        const int gl0 = l0 + r0, gl1 = l0 + r1;
        #pragma unroll
        for (int nt = 0; nt < 8; nt++) {
            #pragma unroll
            for (int j = 0; j < 2; j++) {
                int col = nt*8 + 2*lk + j;
                int gm = m0 + col;
                float cm = msks[col];
                int df0 = gm - gl0;
                if (df0 >= -WW && df0 <= WW) s[nt][j] += relb[r0*12 + df0 + WW];
                if (rmask0 * cm == 0.f) s[nt][j] = -1e4f;
                int df1 = gm - gl1;
                if (df1 >= -WW && df1 <= WW) s[nt][2+j] += relb[r1*12 + df1 + WW];
                if (rmask1 * cm == 0.f) s[nt][2+j] = -1e4f;
            }
        }

        float mx0 = -1e30f, mx1 = -1e30f;
        #pragma unroll
        for (int nt = 0; nt < 8; nt++) {
            mx0 = fmaxf(mx0, fmaxf(s[nt][0], s[nt][1]));
            mx1 = fmaxf(mx1, fmaxf(s[nt][2], s[nt][3]));
        }
        mx0 = fmaxf(mx0, __shfl_xor_sync(0xffffffffu, mx0, 1));
        mx0 = fmaxf(mx0, __shfl_xor_sync(0xffffffffu, mx0, 2));
        mx1 = fmaxf(mx1, __shfl_xor_sync(0xffffffffu, mx1, 1));
        mx1 = fmaxf(mx1, __shfl_xor_sync(0xffffffffu, mx1, 2));

        float nm0 = fmaxf(mi0, mx0), nm1 = fmaxf(mi1, mx1);
        float corr0 = __expf(mi0 - nm0), corr1 = __expf(mi1 - nm1);
        mi0 = nm0; mi1 = nm1;

        float sum0 = 0.f, sum1 = 0.f;
        #pragma unroll
        for (int nt = 0; nt < 8; nt++) {
            s[nt][0] = __expf(s[nt][0] - nm0); s[nt][1] = __expf(s[nt][1] - nm0);
            s[nt][2] = __expf(s[nt][2] - nm1); s[nt][3] = __expf(s[nt][3] - nm1);
            sum0 += s[nt][0] + s[nt][1];
            sum1 += s[nt][2] + s[nt][3];
        }
        sum0 += __shfl_xor_sync(0xffffffffu, sum0, 1);
        sum0 += __shfl_xor_sync(0xffffffffu, sum0, 2);
        sum1 += __shfl_xor_sync(0xffffffffu, sum1, 1);
        sum1 += __shfl_xor_sync(0xffffffffu, sum1, 2);
        li0 = li0 * corr0 + sum0;
        li1 = li1 * corr1 + sum1;

        #pragma unroll
        for (int nt = 0; nt < 8; nt++) {
            co[nt][0] *= corr0; co[nt][1] *= corr0;
            co[nt][2] *= corr1; co[nt][3] *= corr1;
        }

        if (lk == 0) {
            #pragma unroll
            for (int j = 0; j < 9; j++) { pwin[r0*12 + j] *= corr0; pwin[r1*12 + j] *= corr1; }
        }
        __syncwarp();
        #pragma unroll
        for (int nt = 0; nt < 8; nt++) {
            #pragma unroll
            for (int j = 0; j < 2; j++) {
                int gm = m0 + nt*8 + 2*lk + j;
                int df0 = gm - gl0;
                if (df0 >= -WW && df0 <= WW) pwin[r0*12 + df0 + WW] = s[nt][j];
                int df1 = gm - gl1;
                if (df1 >= -WW && df1 <= WW) pwin[r1*12 + df1 + WW] = s[nt][2+j];
            }
        }

        #pragma unroll
        for (int nt = 0; nt < 8; nt++) {
            int c = nt*8 + 2*lk;
            ps[r0*73 + c    ] = __uint_as_float(f2tf(s[nt][0]));
            ps[r0*73 + c + 1] = __uint_as_float(f2tf(s[nt][1]));
            ps[r1*73 + c    ] = __uint_as_float(f2tf(s[nt][2]));
            ps[r1*73 + c + 1] = __uint_as_float(f2tf(s[nt][3]));
        }
        __syncwarp();

        #pragma unroll
        for (int ks8 = 0; ks8 < 64; ks8 += 8) {
            uint32_t a[4];
            a[0] = __float_as_uint(ps[r0*73 + ks8 + lk]);
            a[1] = __float_as_uint(ps[r1*73 + ks8 + lk]);
            a[2] = __float_as_uint(ps[r0*73 + ks8 + lk + 4]);
            a[3] = __float_as_uint(ps[r1*73 + ks8 + lk + 4]);
            #pragma unroll
            for (int nt = 0; nt < 8; nt++) {
                uint32_t bfr[2];
                bfr[0] = __float_as_uint(vs[(nt*8 + lm)*76 + ks8 + lk]);
                bfr[1] = __float_as_uint(vs[(nt*8 + lm)*76 + ks8 + lk + 4]);
                mma_tf32(co[nt], a, bfr);
            }
        }
        __syncthreads();
    }

    float inv0 = 1.0f / li0, inv1 = 1.0f / li1;
    if (lk == 0) { invli[r0] = inv0; invli[r1] = inv1; }
    #pragma unroll
    for (int nt = 0; nt < 8; nt++) {
        int c = nt*8 + 2*lk;
        ps[r0*73 + c    ] = co[nt][0] * inv0;
        ps[r0*73 + c + 1] = co[nt][1] * inv0;
        ps[r1*73 + c    ] = co[nt][2] * inv1;
        ps[r1*73 + c + 1] = co[nt][3] * inv1;
    }
    __syncthreads();

    float* op = O + ((size_t)b * CC + h * DD) * LL;
    #pragma unroll
    for (int i = 0; i < 32; i++) {
        int idx = i * 128 + tid;
        int l = idx & 63;
        int d = idx >> 6;
        float r = 0.f;
        #pragma unroll
        for (int df = 0; df < 9; df++) r = fmaf(pwin[l*12 + df], rvs[df*64 + d], r);
        op[(size_t)d * LL + l0 + l] = ps[l*73 + d] + invli[l] * r;
    }
}

// ---------- fused residual add (2 deltas) + LayerNorm; optional masked ext out ---
// block (16,16), grid (LL/16, BB)
__global__ void add_ln_kernel(const float* __restrict__ X, const float* __restrict__ D0,
                              const float* __restrict__ D1,
                              const float* __restrict__ gam, const float* __restrict__ bet,
                              float* __restrict__ Yo, float* __restrict__ Yext,
                              const float* __restrict__ fm)
{
    int b = blockIdx.y;
    int l = blockIdx.x * 16 + threadIdx.x;
    int cg = threadIdx.y;
    const size_t base = (size_t)b * CC * LL + l;

    float s = 0.f, s2 = 0.f;
    for (int c = cg; c < CC; c += 16) {
        float v = X[base + (size_t)c * LL] + D0[base + (size_t)c * LL] + D1[base + (size_t)c * LL];
        s += v; s2 += v * v;
    }
    __shared__ float sm[16][17], sq[16][17];
    sm[cg][threadIdx.x] = s; sq[cg][threadIdx.x] = s2;
    __syncthreads();
    float ts = 0.f, ts2 = 0.f;
    #pragma unroll
    for (int i = 0; i < 16; i++) { ts += sm[i][threadIdx.x]; ts2 += sq[i][threadIdx.x]; }
    float mean = ts * (1.0f / CC);
    float var  = ts2 * (1.0f / CC) - mean * mean;
    float rstd = rsqrtf(var + EPSC);
    float mval = Yext ? fm[(size_t)b * LL + l] : 0.f;
    for (int c = cg; c < CC; c += 16) {
        float v = X[base + (size_t)c * LL] + D0[base + (size_t)c * LL] + D1[base + (size_t)c * LL];
        float y = (v - mean) * rstd * gam[c] + bet[c];
        Yo[base + (size_t)c * LL] = y;
        if (Yext) Yext[base + (size_t)c * LL] = y * mval;
    }
}

// ---------------- host orchestration -------------------------------------------
extern "C" void kernel_launch(void* const* d_in, const int* in_sizes, int n_in,
                              void* d_out, int out_size)
{
    const float* x    = (const float*)d_in[0];
    const float* mask = (const float*)d_in[1];
    const float* wq = (const float*)d_in[2];  const float* bq = (const float*)d_in[3];
    const float* wk = (const float*)d_in[4];  const float* bk = (const float*)d_in[5];
    const float* wv = (const float*)d_in[6];  const float* bv = (const float*)d_in[7];
    const float* wo = (const float*)d_in[8];  const float* bo = (const float*)d_in[9];
    const float* relk = (const float*)d_in[10];
    const float* relv = (const float*)d_in[11];
    const float* ln1g = (const float*)d_in[12]; const float* ln1b = (const float*)d_in[13];
    const float* w1 = (const float*)d_in[14]; const float* b1 = (const float*)d_in[15];
    const float* w2 = (const float*)d_in[16]; const float* b2 = (const float*)d_in[17];
    const float* ln2g = (const float*)d_in[18]; const float* ln2b = (const float*)d_in[19];

    float *px, *pq, *pk, *pv, *pa, *pt, *ph, *pz;
    cudaGetSymbolAddress((void**)&px, g_x);
    cudaGetSymbolAddress((void**)&pq, g_q);
    cudaGetSymbolAddress((void**)&pk, g_k);
    cudaGetSymbolAddress((void**)&pv, g_v);
    cudaGetSymbolAddress((void**)&pa, g_a);
    cudaGetSymbolAddress((void**)&pt, g_t);
    cudaGetSymbolAddress((void**)&ph, g_h);
    cudaGetSymbolAddress((void**)&pz, g_zero);
    float* pt2 = pk;   // split-K partial #2 (pk free around O-proj / FFN2)

    const size_t attn_smem = (size_t)(64*73*3 + 64*76 + 9*64*2 + 64*12*2 + 64 + 64) * sizeof(float);
    cudaFuncSetAttribute(attn_tc_kernel, cudaFuncAttributeMaxDynamicSharedMemorySize, (int)attn_smem);
    const size_t gemm_smem = (size_t)(3 * STG_A + 3 * STG_B) * sizeof(float);
    cudaFuncSetAttribute(gemm_tc_kernel, cudaFuncAttributeMaxDynamicSharedMemorySize, (int)gemm_smem);

    const int nElem = BB * CC * LL;
    maskmul_kernel<<<nElem / 256, 256>>>(x, mask, px);

    dim3 gQKV(LL / 128, CC / 128, 3 * BB);   // (8,4,12)
    dim3 gSK(LL / 128, CC / 128, 2 * BB);    // (8,4,8) split-K2
    dim3 gF1(LL / 128, FCC / 128, BB);       // (8,16,4)
    dim3 gAttn(LL / 64, HH, BB);             // (16,8,4)
    dim3 gLN(LL / 16, BB);                   // (64,4)
    dim3 bLN(16, 16);

    for (int i = 0; i < NLL; i++) {
        const float* Wq = wq + (size_t)i * CC * CC;
        const float* Wk = wk + (size_t)i * CC * CC;
        const float* Wv = wv + (size_t)i * CC * CC;
        const float* Wo = wo + (size_t)i * CC * CC;
        const float* W1 = w1 + (size_t)i * FCC * CC;
        const float* W2 = w2 + (size_t)i * CC * FCC;
        const bool last = (i == NLL - 1);

        gemm_tc_kernel<<<gQKV, 256, gemm_smem>>>(Wq, Wk, Wv, bq + i*CC, bk + i*CC, bv + i*CC,
                                                 px, mask, pq, pk, pv, CC, LL, CC, 0);

        attn_tc_kernel<<<gAttn, 128, attn_smem>>>(pq, pk, pv, mask,
                                                  relk + (size_t)i * 9 * DD,
                                                  relv + (size_t)i * 9 * DD, pa);

        // O-proj, split-K2 -> pt + pt2
        gemm_tc_kernel<<<gSK, 256, gemm_smem>>>(Wo, Wo, Wo, bo + i*CC, pz, pz,
                                                pa, mask, pt, pt2, pt2, CC, LL, CC, 8);
        add_ln_kernel<<<gLN, bLN>>>(px, pt, pt2, ln1g + i*CC, ln1b + i*CC, px, nullptr, mask);

        gemm_tc_kernel<<<gF1, 256, gemm_smem>>>(W1, W1, W1, b1 + i*FCC, b1 + i*FCC, b1 + i*FCC,
                                                px, mask, ph, ph, ph, FCC, LL, CC, 2 | 4);
        // FFN2, split-K2 -> pt + pt2
        gemm_tc_kernel<<<gSK, 256, gemm_smem>>>(W2, W2, W2, b2 + i*CC, pz, pz,
                                                ph, mask, pt, pt2, pt2, CC, LL, FCC, 8 | 4);
        add_ln_kernel<<<gLN, bLN>>>(px, pt, pt2, ln2g + i*CC, ln2b + i*CC, px,
                                    last ? (float*)d_out : nullptr, mask);
    }
}

// round 7
// speedup vs baseline: 3.5645x; 1.0387x over previous
#include <cuda_runtime.h>
#include <stdint.h>

#define BB  4
#define CC  512
#define LL  1024
#define HH  8
#define DD  64
#define FCC 2048
#define NLL 4
#define WW  4
#define EPSC 1e-6f
#define SCALEC 0.125f   // 64^-0.5

// ---------------- scratch (static device memory; no allocations) ----------------
__device__ float g_x[BB*CC*LL];
__device__ float g_q[BB*CC*LL];
__device__ float g_k[BB*CC*LL];     // also reused as split-K partial #2
__device__ float g_v[BB*CC*LL];
__device__ float g_a[BB*CC*LL];
__device__ float g_t[BB*CC*LL];
__device__ float g_h[(size_t)BB*FCC*LL];
__device__ float g_zero[CC];        // zero-initialized (bias for split-K part 1)
// tf32-rounded weight mirrors
__device__ float g_rwq[NLL*CC*CC];
__device__ float g_rwk[NLL*CC*CC];
__device__ float g_rwv[NLL*CC*CC];
__device__ float g_rwo[NLL*CC*CC];
__device__ float g_rw1[(size_t)NLL*FCC*CC];
__device__ float g_rw2[(size_t)NLL*FCC*CC];

// ---------------- tf32 helpers ---------------------------------------------------
__device__ __forceinline__ uint32_t f2tf(float x) {
    uint32_t t;
    asm volatile("cvt.rna.tf32.f32 %0, %1;" : "=r"(t) : "f"(x));
    return t;
}
__device__ __forceinline__ float rntf(float x) { return __uint_as_float(f2tf(x)); }

__device__ __forceinline__ void mma_tf32(float* c, const uint32_t* a, const uint32_t* b) {
    asm volatile(
        "mma.sync.aligned.m16n8k8.row.col.f32.tf32.tf32.f32 "
        "{%0,%1,%2,%3}, {%4,%5,%6,%7}, {%8,%9}, {%0,%1,%2,%3};\n"
        : "+f"(c[0]), "+f"(c[1]), "+f"(c[2]), "+f"(c[3])
        : "r"(a[0]), "r"(a[1]), "r"(a[2]), "r"(a[3]), "r"(b[0]), "r"(b[1]));
}

__device__ __forceinline__ void cpa16(uint32_t s, const float* g) {
    asm volatile("cp.async.cg.shared.global [%0], [%1], 16;" :: "r"(s), "l"(g));
}

__device__ __forceinline__ void ldm_x4(uint32_t* r, uint32_t a) {
    asm volatile("ldmatrix.sync.aligned.m8n8.x4.shared.b16 {%0,%1,%2,%3}, [%4];"
        : "=r"(r[0]), "=r"(r[1]), "=r"(r[2]), "=r"(r[3]) : "r"(a));
}

// ---------------- prep: round-copy (weights -> tf32-representable mirrors) -------
__global__ void roundcpy_kernel(const float4* __restrict__ X, float4* __restrict__ Y) {
    int i = blockIdx.x * 256 + threadIdx.x;
    float4 v = X[i];
    v.x = rntf(v.x); v.y = rntf(v.y); v.z = rntf(v.z); v.w = rntf(v.w);
    Y[i] = v;
}

// ---------------- elementwise: y = round_tf32(x * mask) --------------------------
__global__ void maskmul_kernel(const float* __restrict__ X, const float* __restrict__ msk,
                               float* __restrict__ Y) {
    int i = blockIdx.x * 256 + threadIdx.x;
    int l = i & (LL - 1);
    int b = i / (CC * LL);
    Y[i] = rntf(X[i] * msk[b * LL + l]);
}

// ---------------- tf32 tensor-core GEMM v4 ---------------------------------------
// Y[b] = W[M,K] @ X[b][K,N] + bias
// flags: 2=relu, 4=mask out cols, 8=split-K2 (mat=k-half), 16=round output to tf32
// All A/B data must be tf32-representable already (raw feed == RN result).
// 256 threads, tile 128x128, warp 64x32, k-step 16, 4-stage cp.async.
#define APAD 20
#define BPAD 136
#define STG_A (128 * APAD)
#define STG_B (16 * BPAD)
#define NSTG 4
__global__ __launch_bounds__(256, 2) void gemm_tc_kernel(
    const float* __restrict__ W0, const float* __restrict__ W1p, const float* __restrict__ W2p,
    const float* __restrict__ c0, const float* __restrict__ c1, const float* __restrict__ c2,
    const float* __restrict__ X, const float* __restrict__ msk,
    float* __restrict__ Y0, float* __restrict__ Y1p, float* __restrict__ Y2p,
    int M, int N, int K, int flags)
{
    extern __shared__ float gsm[];
    float* As = gsm;                   // NSTG stages [m][k] pad 20
    float* Bs = gsm + NSTG * STG_A;    // NSTG stages [k][n] pad 136

    const int tid  = threadIdx.x;
    const int mat  = blockIdx.z / BB;
    const int b    = blockIdx.z % BB;
    const bool splitk = flags & 8;
    const float* Wm   = (mat == 0) ? W0 : (mat == 1 ? W1p : W2p);
    const float* bias = (mat == 0) ? c0 : (mat == 1 ? c1 : c2);
    float*       Y    = (mat == 0) ? Y0 : (mat == 1 ? Y1p : Y2p);

    const int Keff = splitk ? (K >> 1) : K;
    const int kOff = splitk ? mat * Keff : 0;

    const int bm = blockIdx.y * 128, bn = blockIdx.x * 128;
    const float* mp = msk + (size_t)b * LL;

    const float* Ag = Wm + (size_t)bm * K + kOff;
    const float* Bg = X + (size_t)b * K * N + (size_t)kOff * N + bn;

    const int ar  = tid >> 2;
    const int akc = (tid & 3) * 4;
    const int bkk = tid >> 5;
    const int bn4 = (tid & 31) * 4;

    const uint32_t sA = (uint32_t)__cvta_generic_to_shared(As);
    const uint32_t sB = (uint32_t)__cvta_generic_to_shared(Bs);

    #define ISSUE(ST, K0) do { \
        cpa16(sA + (uint32_t)(((ST) * STG_A) + ar * APAD + akc) * 4, \
              Ag + (size_t)ar * K + (K0) + akc); \
        cpa16(sA + (uint32_t)(((ST) * STG_A) + (ar + 64) * APAD + akc) * 4, \
              Ag + (size_t)(ar + 64) * K + (K0) + akc); \
        cpa16(sB + (uint32_t)(((ST) * STG_B) + bkk * BPAD + bn4) * 4, \
              Bg + (size_t)((K0) + bkk) * N + bn4); \
        cpa16(sB + (uint32_t)(((ST) * STG_B) + (bkk + 8) * BPAD + bn4) * 4, \
              Bg + (size_t)((K0) + bkk + 8) * N + bn4); \
        asm volatile("cp.async.commit_group;" ::: "memory"); \
    } while (0)

    const int lane = tid & 31, warp = tid >> 5;
    const int wm = (warp >> 2) * 64;
    const int wn = (warp & 3) * 32;
    const int lm = lane >> 2, lk = lane & 3;
    const int mrow = (lane & 7) + ((lane >> 3) & 1) * 8;
    const int kadd = (lane >> 4) * 4;

    float acc[4][4][4];
    #pragma unroll
    for (int i = 0; i < 4; i++)
        #pragma unroll
        for (int j = 0; j < 4; j++)
            #pragma unroll
            for (int r = 0; r < 4; r++) acc[i][j][r] = 0.f;

    const int nIter = Keff / 16;     // >= 16 always here
    ISSUE(0, 0);
    ISSUE(1, 16);
    ISSUE(2, 32);

    for (int it = 0; it < nIter; it++) {
        if (it + 3 < nIter) ISSUE((it + 3) & 3, (it + 3) * 16);
        else asm volatile("cp.async.commit_group;" ::: "memory");
        asm volatile("cp.async.wait_group 3;" ::: "memory");
        __syncthreads();

        const int buf = it & 3;
        const uint32_t aBase = sA + (uint32_t)(buf * STG_A) * 4;
        const float* Bb = Bs + buf * STG_B;
        #pragma unroll
        for (int ks = 0; ks < 16; ks += 8) {
            uint32_t a[4][4], bfr[4][2];
            #pragma unroll
            for (int mt = 0; mt < 4; mt++)
                ldm_x4(a[mt], aBase + (uint32_t)((wm + mt*16 + mrow) * APAD + ks + kadd) * 4);
            #pragma unroll
            for (int nt = 0; nt < 4; nt++) {
                bfr[nt][0] = __float_as_uint(Bb[(ks + lk    ) * BPAD + wn + nt*8 + lm]);
                bfr[nt][1] = __float_as_uint(Bb[(ks + lk + 4) * BPAD + wn + nt*8 + lm]);
            }
            #pragma unroll
            for (int mt = 0; mt < 4; mt++)
                #pragma unroll
                for (int nt = 0; nt < 4; nt++)
                    mma_tf32(acc[mt][nt], a[mt], bfr[nt]);
        }
        __syncthreads();
    }
    #undef ISSUE

    // ---------------- epilogue ----------------
    const bool relu = flags & 2;
    const bool omask = flags & 4;
    const bool rnd = flags & 16;
    float* Yb = Y + (size_t)b * M * N;
    #pragma unroll
    for (int mt = 0; mt < 4; mt++) {
        #pragma unroll
        for (int half = 0; half < 2; half++) {
            int m = bm + wm + mt * 16 + lm + half * 8;
            float bv = bias[m];
            #pragma unroll
            for (int nt = 0; nt < 4; nt++) {
                int n = bn + wn + nt * 8 + lk * 2;
                float v0 = acc[mt][nt][half * 2 + 0] + bv;
                float v1 = acc[mt][nt][half * 2 + 1] + bv;
                if (relu) { v0 = fmaxf(v0, 0.f); v1 = fmaxf(v1, 0.f); }
                if (rnd)  { v0 = rntf(v0); v1 = rntf(v1); }
                if (omask) { v0 *= mp[n]; v1 *= mp[n + 1]; }
                *(float2*)&Yb[(size_t)m * N + n] = make_float2(v0, v1);
            }
        }
    }
}

// ---------------- tensor-core flash attention v2 ---------------------------------
// grid (L/128, H, B), 256 threads (8 warps x 16 rows). Inputs pre-rounded to tf32.
// Q fragments hoisted to registers (loop-invariant). K/V fills halved per q-row.
__global__ __launch_bounds__(256) void attn_tc_kernel(
    const float* __restrict__ Q, const float* __restrict__ Kk,
    const float* __restrict__ V, const float* __restrict__ msk,
    const float* __restrict__ relk, const float* __restrict__ relv,
    float* __restrict__ O)
{
    extern __shared__ float smem[];
    float* qs    = smem;                 // [128][73] Q tile [l][d] (scaled)
    float* ks_   = qs    + 128 * 73;     // [64][73]  K tile [m][d]
    float* ps    = ks_   + 64 * 73;      // [128][73] P tile [l][m] / unused
    float* vs    = ps    + 128 * 73;     // [64][76]  V tile [d][m]
    float* rks   = vs    + 64 * 76;      // [9][64]
    float* rvs   = rks   + 9 * 64;       // [9][64]
    float* relb  = rvs   + 9 * 64;       // [128][12]
    float* pwin  = relb  + 128 * 12;     // [128][12]
    float* invli = pwin  + 128 * 12;     // [128]
    float* msks  = invli + 128;          // [64]

    const int tid = threadIdx.x;
    const int lane = tid & 31, warp = tid >> 5;
    const int b = blockIdx.z, h = blockIdx.y;
    const int l0 = blockIdx.x * 128;

    const float* qp = Q  + ((size_t)b * CC + h * DD) * LL;
    const float* kp = Kk + ((size_t)b * CC + h * DD) * LL;
    const float* vp = V  + ((size_t)b * CC + h * DD) * LL;
    const float* mp = msk + (size_t)b * LL;

    // ---- stage Q (128 x 64), already tf32; scale by exact power of two ----
    #pragma unroll
    for (int i = 0; i < 8; i++) {
        int d = (tid >> 5) + i * 8;
        int l = (tid & 31) * 4;
        float4 qv = *(const float4*)&qp[(size_t)d * LL + l0 + l];
        qs[(l+0)*73 + d] = qv.x * SCALEC;
        qs[(l+1)*73 + d] = qv.y * SCALEC;
        qs[(l+2)*73 + d] = qv.z * SCALEC;
        qs[(l+3)*73 + d] = qv.w * SCALEC;
    }
    for (int i = tid; i < 9 * 64; i += 256) { rks[i] = relk[i]; rvs[i] = relv[i]; }
    for (int i = tid; i < 128 * 12; i += 256) pwin[i] = 0.f;
    __syncthreads();

    // relbias[l][df] = q_scaled[l] . rel_k[df]  (fp32 precision)
    for (int i = tid; i < 128 * 9; i += 256) {
        int l = i / 9, df = i % 9;
        const float* qq = &qs[l * 73];
        const float* rr = &rks[df * 64];
        float a = 0.f;
        #pragma unroll 16
        for (int d = 0; d < DD; d++) a = fmaf(qq[d], rr[d], a);
        relb[l * 12 + df] = a;
    }

    const int r0 = warp * 16 + (lane >> 2);
    const int r1 = r0 + 8;
    const int lk = lane & 3, lm = lane >> 2;
    const float rmask0 = mp[l0 + r0], rmask1 = mp[l0 + r1];

    // hoist Q fragments (invariant over all k-tiles)
    uint32_t qf[8][4];
    #pragma unroll
    for (int kk = 0; kk < 8; kk++) {
        qf[kk][0] = __float_as_uint(qs[r0*73 + kk*8 + lk]);
        qf[kk][1] = __float_as_uint(qs[r1*73 + kk*8 + lk]);
        qf[kk][2] = __float_as_uint(qs[r0*73 + kk*8 + lk + 4]);
        qf[kk][3] = __float_as_uint(qs[r1*73 + kk*8 + lk + 4]);
    }

    float co[8][4];
    #pragma unroll
    for (int nt = 0; nt < 8; nt++)
        #pragma unroll
        for (int j = 0; j < 4; j++) co[nt][j] = 0.f;
    float mi0 = -1e30f, mi1 = -1e30f, li0 = 0.f, li1 = 0.f;

    __syncthreads();

    for (int t = 0; t < LL / 64; t++) {
        const int m0 = t * 64;
        // ---- stage K [m][d] and V [d][m] (pre-rounded) ----
        #pragma unroll
        for (int i = 0; i < 4; i++) {
            int d = (tid >> 4) + i * 16;
            int m = (tid & 15) * 4;
            float4 kv4 = *(const float4*)&kp[(size_t)d * LL + m0 + m];
            ks_[(m+0)*73 + d] = kv4.x;
            ks_[(m+1)*73 + d] = kv4.y;
            ks_[(m+2)*73 + d] = kv4.z;
            ks_[(m+3)*73 + d] = kv4.w;
            *(float4*)&vs[d * 76 + m] = *(const float4*)&vp[(size_t)d * LL + m0 + m];
        }
        if (tid < 64) msks[tid] = mp[m0 + tid];
        __syncthreads();

        // ---- S = Q K^T ----
        float s[8][4];
        #pragma unroll
        for (int nt = 0; nt < 8; nt++)
            #pragma unroll
            for (int j = 0; j < 4; j++) s[nt][j] = 0.f;

        #pragma unroll
        for (int kk = 0; kk < 8; kk++) {
            #pragma unroll
            for (int nt = 0; nt < 8; nt++) {
                uint32_t bfr[2];
                bfr[0] = __float_as_uint(ks_[(nt*8 + lm)*73 + kk*8 + lk]);
                bfr[1] = __float_as_uint(ks_[(nt*8 + lm)*73 + kk*8 + lk + 4]);
                mma_tf32(s[nt], qf[kk], bfr);
            }
        }

        // ---- rel_k bias + mask ----
        const int gl0 = l0 + r0, gl1 = l0 + r1;
        #pragma unroll
        for (int nt = 0; nt < 8; nt++) {
            #pragma unroll
            for (int j = 0; j < 2; j++) {
                int col = nt*8 + 2*lk + j;
                int gm = m0 + col;
                float cm = msks[col];
                int df0 = gm - gl0;
                if (df0 >= -WW && df0 <= WW) s[nt][j] += relb[r0*12 + df0 + WW];
                if (rmask0 * cm == 0.f) s[nt][j] = -1e4f;
                int df1 = gm - gl1;
                if (df1 >= -WW && df1 <= WW) s[nt][2+j] += relb[r1*12 + df1 + WW];
                if (rmask1 * cm == 0.f) s[nt][2+j] = -1e4f;
            }
        }

        // ---- online softmax ----
        float mx0 = -1e30f, mx1 = -1e30f;
        #pragma unroll
        for (int nt = 0; nt < 8; nt++) {
            mx0 = fmaxf(mx0, fmaxf(s[nt][0], s[nt][1]));
            mx1 = fmaxf(mx1, fmaxf(s[nt][2], s[nt][3]));
        }
        mx0 = fmaxf(mx0, __shfl_xor_sync(0xffffffffu, mx0, 1));
        mx0 = fmaxf(mx0, __shfl_xor_sync(0xffffffffu, mx0, 2));
        mx1 = fmaxf(mx1, __shfl_xor_sync(0xffffffffu, mx1, 1));
        mx1 = fmaxf(mx1, __shfl_xor_sync(0xffffffffu, mx1, 2));

        float nm0 = fmaxf(mi0, mx0), nm1 = fmaxf(mi1, mx1);
        float corr0 = __expf(mi0 - nm0), corr1 = __expf(mi1 - nm1);
        mi0 = nm0; mi1 = nm1;

        float sum0 = 0.f, sum1 = 0.f;
        #pragma unroll
        for (int nt = 0; nt < 8; nt++) {
            s[nt][0] = __expf(s[nt][0] - nm0); s[nt][1] = __expf(s[nt][1] - nm0);
            s[nt][2] = __expf(s[nt][2] - nm1); s[nt][3] = __expf(s[nt][3] - nm1);
            sum0 += s[nt][0] + s[nt][1];
            sum1 += s[nt][2] + s[nt][3];
        }
        sum0 += __shfl_xor_sync(0xffffffffu, sum0, 1);
        sum0 += __shfl_xor_sync(0xffffffffu, sum0, 2);
        sum1 += __shfl_xor_sync(0xffffffffu, sum1, 1);
        sum1 += __shfl_xor_sync(0xffffffffu, sum1, 2);
        li0 = li0 * corr0 + sum0;
        li1 = li1 * corr1 + sum1;

        #pragma unroll
        for (int nt = 0; nt < 8; nt++) {
            co[nt][0] *= corr0; co[nt][1] *= corr0;
            co[nt][2] *= corr1; co[nt][3] *= corr1;
        }

        if (lk == 0) {
            #pragma unroll
            for (int j = 0; j < 9; j++) { pwin[r0*12 + j] *= corr0; pwin[r1*12 + j] *= corr1; }
        }
        __syncwarp();
        #pragma unroll
        for (int nt = 0; nt < 8; nt++) {
            #pragma unroll
            for (int j = 0; j < 2; j++) {
                int gm = m0 + nt*8 + 2*lk + j;
                int df0 = gm - gl0;
                if (df0 >= -WW && df0 <= WW) pwin[r0*12 + df0 + WW] = s[nt][j];
                int df1 = gm - gl1;
                if (df1 >= -WW && df1 <= WW) pwin[r1*12 + df1 + WW] = s[nt][2+j];
            }
        }

        // stage P (own warp rows) rounded to tf32
        #pragma unroll
        for (int nt = 0; nt < 8; nt++) {
            int c = nt*8 + 2*lk;
            ps[r0*73 + c    ] = rntf(s[nt][0]);
            ps[r0*73 + c + 1] = rntf(s[nt][1]);
            ps[r1*73 + c    ] = rntf(s[nt][2]);
            ps[r1*73 + c + 1] = rntf(s[nt][3]);
        }
        __syncwarp();

        // ---- O += P V ----
        #pragma unroll
        for (int kk = 0; kk < 8; kk++) {
            uint32_t a[4];
            a[0] = __float_as_uint(ps[r0*73 + kk*8 + lk]);
            a[1] = __float_as_uint(ps[r1*73 + kk*8 + lk]);
            a[2] = __float_as_uint(ps[r0*73 + kk*8 + lk + 4]);
            a[3] = __float_as_uint(ps[r1*73 + kk*8 + lk + 4]);
            #pragma unroll
            for (int nt = 0; nt < 8; nt++) {
                uint32_t bfr[2];
                bfr[0] = __float_as_uint(vs[(nt*8 + lm)*76 + kk*8 + lk]);
                bfr[1] = __float_as_uint(vs[(nt*8 + lm)*76 + kk*8 + lk + 4]);
                mma_tf32(co[nt], a, bfr);
            }
        }
        __syncthreads();
    }

    // ---- epilogue: normalize, stash [l][d], add rel_v term, store rounded ----
    float inv0 = 1.0f / li0, inv1 = 1.0f / li1;
    if (lk == 0) { invli[r0] = inv0; invli[r1] = inv1; }
    #pragma unroll
    for (int nt = 0; nt < 8; nt++) {
        int c = nt*8 + 2*lk;
        ps[r0*73 + c    ] = co[nt][0] * inv0;
        ps[r0*73 + c + 1] = co[nt][1] * inv0;
        ps[r1*73 + c    ] = co[nt][2] * inv1;
        ps[r1*73 + c + 1] = co[nt][3] * inv1;
    }
    __syncthreads();

    float* op = O + ((size_t)b * CC + h * DD) * LL;
    #pragma unroll
    for (int i = 0; i < 32; i++) {
        int idx = i * 256 + tid;
        int l = idx & 127;
        int d = idx >> 7;
        float r = 0.f;
        #pragma unroll
        for (int df = 0; df < 9; df++) r = fmaf(pwin[l*12 + df], rvs[df*64 + d], r);
        op[(size_t)d * LL + l0 + l] = rntf(ps[l*73 + d] + invli[l] * r);
    }
}

// ---------- fused residual add (2 deltas) + LayerNorm ----------------------------
// Yo rounded to tf32 (GEMM operand); Yext (final output) kept full fp32.
__global__ void add_ln_kernel(const float* __restrict__ X, const float* __restrict__ D0,
                              const float* __restrict__ D1,
                              const float* __restrict__ gam, const float* __restrict__ bet,
                              float* __restrict__ Yo, float* __restrict__ Yext,
                              const float* __restrict__ fm)
{
    int b = blockIdx.y;
    int l = blockIdx.x * 16 + threadIdx.x;
    int cg = threadIdx.y;
    const size_t base = (size_t)b * CC * LL + l;

    float s = 0.f, s2 = 0.f;
    for (int c = cg; c < CC; c += 16) {
        float v = X[base + (size_t)c * LL] + D0[base + (size_t)c * LL] + D1[base + (size_t)c * LL];
        s += v; s2 += v * v;
    }
    __shared__ float sm[16][17], sq[16][17];
    sm[cg][threadIdx.x] = s; sq[cg][threadIdx.x] = s2;
    __syncthreads();
    float ts = 0.f, ts2 = 0.f;
    #pragma unroll
    for (int i = 0; i < 16; i++) { ts += sm[i][threadIdx.x]; ts2 += sq[i][threadIdx.x]; }
    float mean = ts * (1.0f / CC);
    float var  = ts2 * (1.0f / CC) - mean * mean;
    float rstd = rsqrtf(var + EPSC);
    float mval = Yext ? fm[(size_t)b * LL + l] : 0.f;
    for (int c = cg; c < CC; c += 16) {
        float v = X[base + (size_t)c * LL] + D0[base + (size_t)c * LL] + D1[base + (size_t)c * LL];
        float y = (v - mean) * rstd * gam[c] + bet[c];
        Yo[base + (size_t)c * LL] = rntf(y);
        if (Yext) Yext[base + (size_t)c * LL] = y * mval;
    }
}

// ---------------- host orchestration -------------------------------------------
extern "C" void kernel_launch(void* const* d_in, const int* in_sizes, int n_in,
                              void* d_out, int out_size)
{
    const float* x    = (const float*)d_in[0];
    const float* mask = (const float*)d_in[1];
    const float* wq = (const float*)d_in[2];  const float* bq = (const float*)d_in[3];
    const float* wk = (const float*)d_in[4];  const float* bk = (const float*)d_in[5];
    const float* wv = (const float*)d_in[6];  const float* bv = (const float*)d_in[7];
    const float* wo = (const float*)d_in[8];  const float* bo = (const float*)d_in[9];
    const float* relk = (const float*)d_in[10];
    const float* relv = (const float*)d_in[11];
    const float* ln1g = (const float*)d_in[12]; const float* ln1b = (const float*)d_in[13];
    const float* w1 = (const float*)d_in[14]; const float* b1 = (const float*)d_in[15];
    const float* w2 = (const float*)d_in[16]; const float* b2 = (const float*)d_in[17];
    const float* ln2g = (const float*)d_in[18]; const float* ln2b = (const float*)d_in[19];

    float *px, *pq, *pk, *pv, *pa, *pt, *ph, *pz;
    float *rwq, *rwk, *rwv, *rwo, *rw1, *rw2;
    cudaGetSymbolAddress((void**)&px, g_x);
    cudaGetSymbolAddress((void**)&pq, g_q);
    cudaGetSymbolAddress((void**)&pk, g_k);
    cudaGetSymbolAddress((void**)&pv, g_v);
    cudaGetSymbolAddress((void**)&pa, g_a);
    cudaGetSymbolAddress((void**)&pt, g_t);
    cudaGetSymbolAddress((void**)&ph, g_h);
    cudaGetSymbolAddress((void**)&pz, g_zero);
    cudaGetSymbolAddress((void**)&rwq, g_rwq);
    cudaGetSymbolAddress((void**)&rwk, g_rwk);
    cudaGetSymbolAddress((void**)&rwv, g_rwv);
    cudaGetSymbolAddress((void**)&rwo, g_rwo);
    cudaGetSymbolAddress((void**)&rw1, g_rw1);
    cudaGetSymbolAddress((void**)&rw2, g_rw2);
    float* pt2 = pk;   // split-K partial #2 (pk free around O-proj / FFN2)

    const size_t attn_smem = (size_t)(128*73 + 64*73 + 128*73 + 64*76 + 9*64*2
                                      + 128*12*2 + 128 + 64) * sizeof(float);
    cudaFuncSetAttribute(attn_tc_kernel, cudaFuncAttributeMaxDynamicSharedMemorySize, (int)attn_smem);
    const size_t gemm_smem = (size_t)(NSTG * STG_A + NSTG * STG_B) * sizeof(float);
    cudaFuncSetAttribute(gemm_tc_kernel, cudaFuncAttributeMaxDynamicSharedMemorySize, (int)gemm_smem);

    // ---- weight prep: tf32-round mirrors (pure bandwidth, ~25us) ----
    const int nW = NLL * CC * CC / 4;       // float4 count
    const int nF = NLL * FCC * CC / 4;
    roundcpy_kernel<<<nW / 256, 256>>>((const float4*)wq, (float4*)rwq);
    roundcpy_kernel<<<nW / 256, 256>>>((const float4*)wk, (float4*)rwk);
    roundcpy_kernel<<<nW / 256, 256>>>((const float4*)wv, (float4*)rwv);
    roundcpy_kernel<<<nW / 256, 256>>>((const float4*)wo, (float4*)rwo);
    roundcpy_kernel<<<nF / 256, 256>>>((const float4*)w1, (float4*)rw1);
    roundcpy_kernel<<<nF / 256, 256>>>((const float4*)w2, (float4*)rw2);

    const int nElem = BB * CC * LL;
    maskmul_kernel<<<nElem / 256, 256>>>(x, mask, px);

    dim3 gQKV(LL / 128, CC / 128, 3 * BB);   // (8,4,12)
    dim3 gSK(LL / 128, CC / 128, 2 * BB);    // (8,4,8) split-K2
    dim3 gF1(LL / 128, FCC / 128, BB);       // (8,16,4)
    dim3 gAttn(LL / 128, HH, BB);            // (8,8,4)
    dim3 gLN(LL / 16, BB);
    dim3 bLN(16, 16);

    for (int i = 0; i < NLL; i++) {
        const float* Wq = rwq + (size_t)i * CC * CC;
        const float* Wk = rwk + (size_t)i * CC * CC;
        const float* Wv = rwv + (size_t)i * CC * CC;
        const float* Wo = rwo + (size_t)i * CC * CC;
        const float* W1 = rw1 + (size_t)i * FCC * CC;
        const float* W2 = rw2 + (size_t)i * CC * FCC;
        const bool last = (i == NLL - 1);

        gemm_tc_kernel<<<gQKV, 256, gemm_smem>>>(Wq, Wk, Wv, bq + i*CC, bk + i*CC, bv + i*CC,
                                                 px, mask, pq, pk, pv, CC, LL, CC, 16);

        attn_tc_kernel<<<gAttn, 256, attn_smem>>>(pq, pk, pv, mask,
                                                  relk + (size_t)i * 9 * DD,
                                                  relv + (size_t)i * 9 * DD, pa);

        // O-proj, split-K2 -> pt + pt2 (partials unrounded)
        gemm_tc_kernel<<<gSK, 256, gemm_smem>>>(Wo, Wo, Wo, bo + i*CC, pz, pz,
                                                pa, mask, pt, pt2, pt2, CC, LL, CC, 8);
        add_ln_kernel<<<gLN, bLN>>>(px, pt, pt2, ln1g + i*CC, ln1b + i*CC, px, nullptr, mask);

        gemm_tc_kernel<<<gF1, 256, gemm_smem>>>(W1, W1, W1, b1 + i*FCC, b1 + i*FCC, b1 + i*FCC,
                                                px, mask, ph, ph, ph, FCC, LL, CC, 2 | 4 | 16);
        // FFN2, split-K2 -> pt + pt2
        gemm_tc_kernel<<<gSK, 256, gemm_smem>>>(W2, W2, W2, b2 + i*CC, pz, pz,
                                                ph, mask, pt, pt2, pt2, CC, LL, FCC, 8 | 4);
        add_ln_kernel<<<gLN, bLN>>>(px, pt, pt2, ln2g + i*CC, ln2b + i*CC, px,
                                    last ? (float*)d_out : nullptr, mask);
    }
}